// round 1
// baseline (speedup 1.0000x reference)
#include <cuda_runtime.h>
#include <math.h>

// Problem constants
#define PP   256        // patches per (b,m)
#define DD   512        // model dim
#define HA   256        // H*A
#define SHIFT 2
#define TOKS 65536      // B*M*P

// ---------------- scratch (device globals; allocation-free rule) -------------
__device__ float g_Q[(size_t)TOKS * HA];
__device__ float g_K[(size_t)TOKS * HA];
__device__ float g_V[(size_t)TOKS * HA];
__device__ float g_Z[(size_t)TOKS * HA];
__device__ float g_z1[(size_t)TOKS * DD];
__device__ float g_o2[(size_t)TOKS * DD];

typedef unsigned long long u64;

// ---------------- f32x2 packed helpers (Blackwell 2xFP32 path) ---------------
__device__ __forceinline__ void fma2(u64 &d, u64 a, u64 b) {
    asm("fma.rn.f32x2 %0, %1, %2, %0;" : "+l"(d) : "l"(a), "l"(b));
}
__device__ __forceinline__ u64 bcast2(float x) {
    u64 r; asm("mov.b64 %0, {%1, %1};" : "=l"(r) : "f"(x)); return r;
}
__device__ __forceinline__ u64 pack2(float lo, float hi) {
    u64 r; asm("mov.b64 %0, {%1, %2};" : "=l"(r) : "f"(lo), "f"(hi)); return r;
}
__device__ __forceinline__ float2 unpk(u64 v) {
    float2 f; asm("mov.b64 {%0, %1}, %2;" : "=f"(f.x), "=f"(f.y) : "l"(v)); return f;
}

enum { MQKV = 0, MPROJ = 1, MFFN = 2, MMERGE = 3 };

// =============================================================================
// Fused GEMM: C[rows x BN] = gather(A)[rows x K] @ W[BN x K]^T + bias, then
// mode-specific epilogue (LN / shift / residual / relu). Block = 32 rows x BN.
// 256 threads; each thread owns 32/TY rows x 8 strided columns (4 f32x2 accs).
// =============================================================================
template<int MODE, int BN, int K>
__global__ void __launch_bounds__(256) gemm_k(
    const float* __restrict__ Ax,   // x (QKV gather / PROJ residual); else unused
    const float* __restrict__ W_0, const float* __restrict__ b_0,
    const float* __restrict__ W_1, const float* __restrict__ b_1,
    const float* __restrict__ W_2, const float* __restrict__ b_2,
    const float* __restrict__ gamma, const float* __restrict__ beta,
    float* __restrict__ dOut)
{
    constexpr int TX  = BN / 8;       // threads across columns
    constexpr int TY  = 256 / TX;     // thread groups across rows
    constexpr int RPT = 32 / TY;      // rows per thread

    const int tid = threadIdx.x;
    const int tx = tid % TX, ty = tid / TX;
    const int bx = blockIdx.x;

    const float* W = W_0;
    const float* Bv = b_0;
    float* Obuf = nullptr;
    if constexpr (MODE == MQKV) {
        const int wsel = blockIdx.y;
        W    = (wsel == 0) ? W_0 : (wsel == 1) ? W_1 : W_2;
        Bv   = (wsel == 0) ? b_0 : (wsel == 1) ? b_1 : b_2;
        Obuf = (wsel == 0) ? g_Q : (wsel == 1) ? g_K : g_V;
    }

    __shared__ float  As[32][8];
    __shared__ float  Bs[8][BN];
    __shared__ float2 red[32][TX];
    __shared__ float  s_mu[32], s_rs[32];

    // ---- A-tile load slot: thread (lr, lk) loads As[lr][lk]
    const int lr = tid >> 3, lk = tid & 7;
    const int rgl = bx * 32 + lr;
    const float* aptr;
    int mtokbase = 0;
    if constexpr (MODE == MQKV) {
        const int srow = (rgl & ~(PP - 1)) | ((rgl + SHIFT) & (PP - 1)); // xs = roll(x,-2)
        aptr = Ax + (size_t)srow * DD;
    } else if constexpr (MODE == MPROJ) {
        aptr = g_Z + (size_t)rgl * HA;
    } else if constexpr (MODE == MFFN) {
        aptr = g_z1 + (size_t)rgl * DD;
    } else { // MMERGE: row rgl -> concat(o2[tok], o2[tok+1])
        mtokbase = ((rgl >> 7) << 8) + ((rgl & 127) << 1);
        aptr = g_o2;
    }

    u64 acc[RPT][4];
    #pragma unroll
    for (int i = 0; i < RPT; i++)
        #pragma unroll
        for (int j = 0; j < 4; j++) acc[i][j] = 0ull;

    for (int k0 = 0; k0 < K; k0 += 8) {
        // A tile
        if constexpr (MODE == MMERGE) {
            const int k = k0 + lk;
            As[lr][lk] = aptr[(size_t)(mtokbase + (k >> 9)) * DD + (k & (DD - 1))];
        } else {
            As[lr][lk] = aptr[k0 + lk];
        }
        // B tile: Bs[kk][n] = W[n][k0+kk]; thread loads 8 contiguous k for n-rows
        #pragma unroll
        for (int i = 0; i < BN / 256; i++) {
            const int n = tid + i * 256;
            const float4 u0 = *(const float4*)&W[(size_t)n * K + k0];
            const float4 u1 = *(const float4*)&W[(size_t)n * K + k0 + 4];
            Bs[0][n] = u0.x; Bs[1][n] = u0.y; Bs[2][n] = u0.z; Bs[3][n] = u0.w;
            Bs[4][n] = u1.x; Bs[5][n] = u1.y; Bs[6][n] = u1.z; Bs[7][n] = u1.w;
        }
        __syncthreads();
        #pragma unroll
        for (int kk = 0; kk < 8; kk++) {
            u64 bp[4];
            #pragma unroll
            for (int j = 0; j < 4; j++)
                bp[j] = pack2(Bs[kk][tx + (2 * j) * TX], Bs[kk][tx + (2 * j + 1) * TX]);
            #pragma unroll
            for (int ri = 0; ri < RPT; ri++) {
                const u64 a2 = bcast2(As[ty * RPT + ri][kk]);
                fma2(acc[ri][0], a2, bp[0]);
                fma2(acc[ri][1], a2, bp[1]);
                fma2(acc[ri][2], a2, bp[2]);
                fma2(acc[ri][3], a2, bp[3]);
            }
        }
        __syncthreads();
    }

    // ---- bias for this thread's 8 strided columns
    float bb[8];
    #pragma unroll
    for (int j = 0; j < 8; j++) bb[j] = Bv[tx + j * TX];

    if constexpr (MODE == MQKV) {
        #pragma unroll
        for (int ri = 0; ri < RPT; ri++) {
            const int rg = bx * 32 + ty * RPT + ri;
            float* op = Obuf + (size_t)rg * BN;
            #pragma unroll
            for (int j = 0; j < 4; j++) {
                const float2 p = unpk(acc[ri][j]);
                op[tx + (2 * j) * TX]     = p.x + bb[2 * j];
                op[tx + (2 * j + 1) * TX] = p.y + bb[2 * j + 1];
            }
        }
    } else {
        float gg[8], be[8];
        #pragma unroll
        for (int j = 0; j < 8; j++) { gg[j] = gamma[tx + j * TX]; be[j] = beta[tx + j * TX]; }

        // row stats (LN over BN == 512 == D)
        #pragma unroll
        for (int ri = 0; ri < RPT; ri++) {
            float s = 0.f, q = 0.f;
            #pragma unroll
            for (int j = 0; j < 4; j++) {
                const float2 p = unpk(acc[ri][j]);
                const float a = p.x + bb[2 * j], c = p.y + bb[2 * j + 1];
                s += a + c; q += a * a + c * c;
            }
            red[ty * RPT + ri][tx] = make_float2(s, q);
        }
        __syncthreads();
        if (tid < 32) {
            float s = 0.f, q = 0.f;
            #pragma unroll 8
            for (int i = 0; i < TX; i++) { const float2 p = red[tid][i]; s += p.x; q += p.y; }
            const float mu  = s * (1.0f / BN);
            const float var = q * (1.0f / BN) - mu * mu;
            s_mu[tid] = mu; s_rs[tid] = rsqrtf(var + 1e-5f);
        }
        __syncthreads();

        #pragma unroll
        for (int ri = 0; ri < RPT; ri++) {
            const int rl = ty * RPT + ri, rg = bx * 32 + rl;
            const float mu = s_mu[rl], rs = s_rs[rl];
            float v[8];
            #pragma unroll
            for (int j = 0; j < 4; j++) {
                const float2 p = unpk(acc[ri][j]);
                v[2 * j]     = p.x + bb[2 * j];
                v[2 * j + 1] = p.y + bb[2 * j + 1];
            }
            #pragma unroll
            for (int j = 0; j < 8; j++) v[j] = (v[j] - mu) * rs * gg[j] + be[j];

            if constexpr (MODE == MPROJ) {
                // z computed in shifted space at p_s lands at p_s + SHIFT (roll +2)
                const int dtok = (rg & ~(PP - 1)) | ((rg + SHIFT) & (PP - 1));
                const float* xr = Ax   + (size_t)dtok * DD;
                float*       op = g_z1 + (size_t)dtok * DD;
                #pragma unroll
                for (int j = 0; j < 8; j++)
                    op[tx + j * TX] = fmaxf(xr[tx + j * TX] + v[j], 0.f);
            } else if constexpr (MODE == MFFN) {
                const float* zr = g_z1 + (size_t)rg * DD;
                float*       op = g_o2 + (size_t)rg * DD;
                #pragma unroll
                for (int j = 0; j < 8; j++)
                    op[tx + j * TX] = fmaxf(zr[tx + j * TX] + v[j], 0.f);
            } else { // MMERGE
                float* op = dOut + (size_t)rg * DD;
                #pragma unroll
                for (int j = 0; j < 8; j++)
                    op[tx + j * TX] = fmaxf(v[j], 0.f);
            }
        }
    }
}

// =============================================================================
// Windowed attention: 1 warp per (window, head). WS=4, A=64.
// Only window index 63 within each (b,m) carries the shift mask (-100 cross).
// =============================================================================
__global__ void __launch_bounds__(256) attn_k() {
    const int task = blockIdx.x * 8 + (threadIdx.x >> 5);  // 65536 tasks
    const int lane = threadIdx.x & 31;
    const int w = task >> 2, h = task & 3;
    const size_t base = (size_t)(w << 2) * HA + (h << 6) + lane;

    float q0[4], q1[4], k0v[4], k1v[4], v0[4], v1[4];
    #pragma unroll
    for (int r = 0; r < 4; r++) {
        q0[r]  = g_Q[base + (size_t)r * HA];  q1[r]  = g_Q[base + (size_t)r * HA + 32];
        k0v[r] = g_K[base + (size_t)r * HA];  k1v[r] = g_K[base + (size_t)r * HA + 32];
        v0[r]  = g_V[base + (size_t)r * HA];  v1[r]  = g_V[base + (size_t)r * HA + 32];
    }

    float s[4][4];
    #pragma unroll
    for (int r = 0; r < 4; r++)
        #pragma unroll
        for (int c = 0; c < 4; c++) {
            float p = q0[r] * k0v[c] + q1[r] * k1v[c];
            #pragma unroll
            for (int m = 16; m >= 1; m >>= 1) p += __shfl_xor_sync(0xffffffffu, p, m);
            s[r][c] = p * 0.125f;  // 1/sqrt(64)
        }

    if ((w & 63) == 63) {
        #pragma unroll
        for (int r = 0; r < 4; r++)
            #pragma unroll
            for (int c = 0; c < 4; c++)
                if ((r < 2) != (c < 2)) s[r][c] -= 100.0f;
    }

    #pragma unroll
    for (int r = 0; r < 4; r++) {
        const float m = fmaxf(fmaxf(s[r][0], s[r][1]), fmaxf(s[r][2], s[r][3]));
        const float e0 = expf(s[r][0] - m), e1 = expf(s[r][1] - m);
        const float e2 = expf(s[r][2] - m), e3 = expf(s[r][3] - m);
        const float inv = 1.0f / (e0 + e1 + e2 + e3);
        g_Z[base + (size_t)r * HA]      = (e0 * v0[0] + e1 * v0[1] + e2 * v0[2] + e3 * v0[3]) * inv;
        g_Z[base + (size_t)r * HA + 32] = (e0 * v1[0] + e1 * v1[1] + e2 * v1[2] + e3 * v1[3]) * inv;
    }
}

// =============================================================================
extern "C" void kernel_launch(void* const* d_in, const int* in_sizes, int n_in,
                              void* d_out, int out_size) {
    (void)in_sizes; (void)n_in; (void)out_size;
    const float* x     = (const float*)d_in[0];
    const float* Wq    = (const float*)d_in[1];
    const float* bq    = (const float*)d_in[2];
    const float* Wk    = (const float*)d_in[3];
    const float* bk    = (const float*)d_in[4];
    const float* Wv    = (const float*)d_in[5];
    const float* bv    = (const float*)d_in[6];
    const float* aW    = (const float*)d_in[7];
    const float* ab    = (const float*)d_in[8];
    const float* ag    = (const float*)d_in[9];
    const float* abeta = (const float*)d_in[10];
    const float* fW    = (const float*)d_in[11];
    const float* fb    = (const float*)d_in[12];
    const float* fg    = (const float*)d_in[13];
    const float* fbeta = (const float*)d_in[14];
    const float* dW    = (const float*)d_in[15];
    const float* db    = (const float*)d_in[16];
    const float* dg    = (const float*)d_in[17];
    const float* dbeta = (const float*)d_in[18];
    float* out = (float*)d_out;

    // 1) QKV projections on shifted tokens (grid.y selects Wq/Wk/Wv)
    gemm_k<MQKV, 256, 512><<<dim3(TOKS / 32, 3, 1), 256>>>(
        x, Wq, bq, Wk, bk, Wv, bv, nullptr, nullptr, nullptr);

    // 2) windowed attention -> g_Z
    attn_k<<<TOKS * 4 / (4 * 8), 256>>>();   // 8192 blocks, 8 warps each

    // 3) attn proj + LN + reverse shift + relu(x + .) -> g_z1
    gemm_k<MPROJ, 512, 256><<<TOKS / 32, 256>>>(
        x, aW, ab, nullptr, nullptr, nullptr, nullptr, ag, abeta, nullptr);

    // 4) FFN + LN + relu(z1 + .) -> g_o2
    gemm_k<MFFN, 512, 512><<<TOKS / 32, 256>>>(
        nullptr, fW, fb, nullptr, nullptr, nullptr, nullptr, fg, fbeta, nullptr);

    // 5) patch merge (K=1024 concat gather) + LN + relu -> d_out
    gemm_k<MMERGE, 512, 1024><<<(TOKS / 2) / 32, 256>>>(
        nullptr, dW, db, nullptr, nullptr, nullptr, nullptr, dg, dbeta, out);
}

// round 2
// speedup vs baseline: 1.3919x; 1.3919x over previous
#include <cuda_runtime.h>
#include <math.h>

// Problem constants
#define PP   256        // patches per (b,m)
#define DD   512        // model dim
#define HA   256        // H*A
#define SHIFT 2
#define TOKS 65536      // B*M*P

// ---------------- scratch (device globals; allocation-free rule) -------------
__device__ float g_Q[(size_t)TOKS * HA];
__device__ float g_K[(size_t)TOKS * HA];
__device__ float g_V[(size_t)TOKS * HA];
__device__ float g_Z[(size_t)TOKS * HA];
__device__ float g_z1[(size_t)TOKS * DD];
__device__ float g_o2[(size_t)TOKS * DD];

typedef unsigned long long u64;

// ---------------- f32x2 packed helpers (Blackwell 2xFP32 path) ---------------
__device__ __forceinline__ void fma2(u64 &d, u64 a, u64 b) {
    asm("fma.rn.f32x2 %0, %1, %2, %0;" : "+l"(d) : "l"(a), "l"(b));
}
__device__ __forceinline__ u64 bcast2(float x) {
    u64 r; asm("mov.b64 %0, {%1, %1};" : "=l"(r) : "f"(x)); return r;
}
__device__ __forceinline__ u64 pack2(float lo, float hi) {
    u64 r; asm("mov.b64 %0, {%1, %2};" : "=l"(r) : "f"(lo), "f"(hi)); return r;
}
__device__ __forceinline__ float2 unpk(u64 v) {
    float2 f; asm("mov.b64 {%0, %1}, %2;" : "=f"(f.x), "=f"(f.y) : "l"(v)); return f;
}

enum { MQKV = 0, MPROJ = 1, MFFN = 2, MMERGE = 3 };

// =============================================================================
// Fused GEMM: C[ROWS x BN] = gather(A)[ROWS x K] @ W[BN x K]^T + bias, then
// mode-specific epilogue. 256 threads. Thread tile = 8 rows x 8 cols
// (two contiguous 4-col groups at tx*4 and tx*4+BN/2). Double-buffered smem,
// k-major tiles, vectorized LDS.128 frags (A broadcast, B conflict-free).
// =============================================================================
template<int MODE, int BN, int K, int ROWS>
__global__ void __launch_bounds__(256) gemm_k(
    const float* __restrict__ Ax,
    const float* __restrict__ W_0, const float* __restrict__ b_0,
    const float* __restrict__ W_1, const float* __restrict__ b_1,
    const float* __restrict__ W_2, const float* __restrict__ b_2,
    const float* __restrict__ gamma, const float* __restrict__ beta,
    float* __restrict__ dOut)
{
    constexpr int TX  = BN / 8;       // threads across columns (64 or 32)
    constexpr int TY  = 256 / TX;     // row groups (4 or 8)
    constexpr int RPT = ROWS / TY;    // rows per thread (=8)
    constexpr int GS  = BN / 2;       // col-group stride
    constexpr int NB  = BN / 256;     // W n-rows fetched per thread per stage
    constexpr int NA  = ROWS / 32;    // A rows fetched per fill-thread

    const int tid = threadIdx.x;
    const int tx = tid % TX, ty = tid / TX;
    const int bx = blockIdx.x;

    const float* W = W_0;
    const float* Bv = b_0;
    float* Obuf = nullptr;
    if constexpr (MODE == MQKV) {
        const int wsel = blockIdx.y;
        W    = (wsel == 0) ? W_0 : (wsel == 1) ? W_1 : W_2;
        Bv   = (wsel == 0) ? b_0 : (wsel == 1) ? b_1 : b_2;
        Obuf = (wsel == 0) ? g_Q : (wsel == 1) ? g_K : g_V;
    }

    __shared__ float As[2][8][ROWS];
    __shared__ float Bs[2][8][BN];
    __shared__ float s_mu[32], s_rs[32];

    // ---- A fill slot: thread (lr, lk) covers As[lk][lr (+32)]
    const int lr = tid >> 3, lk = tid & 7;
    const float* aRow[NA];
    int mtok[NA];
    #pragma unroll
    for (int na = 0; na < NA; na++) {
        const int rgl = bx * ROWS + lr + na * 32;
        if constexpr (MODE == MQKV) {
            const int srow = (rgl & ~(PP - 1)) | ((rgl + SHIFT) & (PP - 1));
            aRow[na] = Ax + (size_t)srow * DD;
        } else if constexpr (MODE == MPROJ) {
            aRow[na] = g_Z + (size_t)rgl * HA;
        } else if constexpr (MODE == MFFN) {
            aRow[na] = g_z1 + (size_t)rgl * DD;
        } else {
            mtok[na] = ((rgl >> 7) << 8) + ((rgl & 127) << 1);
            aRow[na] = g_o2;
        }
    }

    u64 acc[RPT][4];
    #pragma unroll
    for (int i = 0; i < RPT; i++)
        #pragma unroll
        for (int j = 0; j < 4; j++) acc[i][j] = 0ull;

    float  areg[NA];
    float4 breg[NB][2];

    auto fetch = [&](int k0) {
        #pragma unroll
        for (int na = 0; na < NA; na++) {
            if constexpr (MODE == MMERGE) {
                const int k = k0 + lk;
                areg[na] = aRow[na][(size_t)(mtok[na] + (k >> 9)) * DD + (k & (DD - 1))];
            } else {
                areg[na] = aRow[na][k0 + lk];
            }
        }
        #pragma unroll
        for (int nb = 0; nb < NB; nb++) {
            const int n = tid + nb * 256;
            breg[nb][0] = *(const float4*)&W[(size_t)n * K + k0];
            breg[nb][1] = *(const float4*)&W[(size_t)n * K + k0 + 4];
        }
    };
    auto stage = [&](int buf) {
        #pragma unroll
        for (int na = 0; na < NA; na++) As[buf][lk][lr + na * 32] = areg[na];
        #pragma unroll
        for (int nb = 0; nb < NB; nb++) {
            const int n = tid + nb * 256;
            Bs[buf][0][n] = breg[nb][0].x; Bs[buf][1][n] = breg[nb][0].y;
            Bs[buf][2][n] = breg[nb][0].z; Bs[buf][3][n] = breg[nb][0].w;
            Bs[buf][4][n] = breg[nb][1].x; Bs[buf][5][n] = breg[nb][1].y;
            Bs[buf][6][n] = breg[nb][1].z; Bs[buf][7][n] = breg[nb][1].w;
        }
    };
    auto compute = [&](int buf) {
        #pragma unroll
        for (int kk = 0; kk < 8; kk++) {
            const float4 a0 = *(const float4*)&As[buf][kk][ty * RPT];
            const float4 a1 = *(const float4*)&As[buf][kk][ty * RPT + 4];
            const float4 b0 = *(const float4*)&Bs[buf][kk][tx * 4];
            const float4 b1 = *(const float4*)&Bs[buf][kk][tx * 4 + GS];
            u64 bp[4];
            bp[0] = pack2(b0.x, b0.y); bp[1] = pack2(b0.z, b0.w);
            bp[2] = pack2(b1.x, b1.y); bp[3] = pack2(b1.z, b1.w);
            const float ar[8] = {a0.x, a0.y, a0.z, a0.w, a1.x, a1.y, a1.z, a1.w};
            #pragma unroll
            for (int r = 0; r < RPT; r++) {
                const u64 a2 = bcast2(ar[r]);
                fma2(acc[r][0], a2, bp[0]);
                fma2(acc[r][1], a2, bp[1]);
                fma2(acc[r][2], a2, bp[2]);
                fma2(acc[r][3], a2, bp[3]);
            }
        }
    };

    fetch(0);
    stage(0);
    __syncthreads();
    int buf = 0;
    for (int k0 = 8; k0 < K; k0 += 8) {
        fetch(k0);
        compute(buf);
        stage(buf ^ 1);
        __syncthreads();
        buf ^= 1;
    }
    compute(buf);

    // ---- bias for this thread's 8 cols (two contiguous groups of 4)
    const float4 bv0 = *(const float4*)&Bv[tx * 4];
    const float4 bv1 = *(const float4*)&Bv[tx * 4 + GS];
    const float bb[8] = {bv0.x, bv0.y, bv0.z, bv0.w, bv1.x, bv1.y, bv1.z, bv1.w};

    if constexpr (MODE == MQKV) {
        #pragma unroll
        for (int ri = 0; ri < RPT; ri++) {
            const int rg = bx * ROWS + ty * RPT + ri;
            float* op = Obuf + (size_t)rg * BN;
            const float2 p0 = unpk(acc[ri][0]), p1 = unpk(acc[ri][1]);
            const float2 p2 = unpk(acc[ri][2]), p3 = unpk(acc[ri][3]);
            *(float4*)&op[tx * 4]      = make_float4(p0.x + bb[0], p0.y + bb[1], p1.x + bb[2], p1.y + bb[3]);
            *(float4*)&op[tx * 4 + GS] = make_float4(p2.x + bb[4], p2.y + bb[5], p3.x + bb[6], p3.y + bb[7]);
        }
    } else {
        const float4 gg0 = *(const float4*)&gamma[tx * 4];
        const float4 gg1 = *(const float4*)&gamma[tx * 4 + GS];
        const float4 be0 = *(const float4*)&beta[tx * 4];
        const float4 be1 = *(const float4*)&beta[tx * 4 + GS];
        const float gg[8] = {gg0.x, gg0.y, gg0.z, gg0.w, gg1.x, gg1.y, gg1.z, gg1.w};
        const float be[8] = {be0.x, be0.y, be0.z, be0.w, be1.x, be1.y, be1.z, be1.w};

        __syncthreads();   // done reading Bs; reuse its storage for reductions
        float2* red = (float2*)&Bs[0][0][0];   // [32][TX+1] padded

        #pragma unroll
        for (int ri = 0; ri < RPT; ri++) {
            float s = 0.f, q = 0.f;
            #pragma unroll
            for (int j = 0; j < 4; j++) {
                const float2 p = unpk(acc[ri][j]);
                const float a = p.x + bb[2 * j], c = p.y + bb[2 * j + 1];
                s += a + c; q += a * a + c * c;
            }
            red[(ty * RPT + ri) * (TX + 1) + tx] = make_float2(s, q);
        }
        __syncthreads();
        if (tid < 32) {
            float s = 0.f, q = 0.f;
            #pragma unroll 8
            for (int i = 0; i < TX; i++) {
                const float2 p = red[tid * (TX + 1) + i];
                s += p.x; q += p.y;
            }
            const float mu  = s * (1.0f / BN);
            const float var = q * (1.0f / BN) - mu * mu;
            s_mu[tid] = mu; s_rs[tid] = rsqrtf(var + 1e-5f);
        }
        __syncthreads();

        #pragma unroll
        for (int ri = 0; ri < RPT; ri++) {
            const int rl = ty * RPT + ri, rg = bx * ROWS + rl;
            const float mu = s_mu[rl], rs = s_rs[rl];
            float v[8];
            #pragma unroll
            for (int j = 0; j < 4; j++) {
                const float2 p = unpk(acc[ri][j]);
                v[2 * j]     = p.x + bb[2 * j];
                v[2 * j + 1] = p.y + bb[2 * j + 1];
            }
            #pragma unroll
            for (int j = 0; j < 8; j++) v[j] = (v[j] - mu) * rs * gg[j] + be[j];

            if constexpr (MODE == MPROJ) {
                const int dtok = (rg & ~(PP - 1)) | ((rg + SHIFT) & (PP - 1));
                const float* xr = Ax   + (size_t)dtok * DD;
                float*       op = g_z1 + (size_t)dtok * DD;
                const float4 x0 = *(const float4*)&xr[tx * 4];
                const float4 x1 = *(const float4*)&xr[tx * 4 + GS];
                *(float4*)&op[tx * 4] = make_float4(
                    fmaxf(x0.x + v[0], 0.f), fmaxf(x0.y + v[1], 0.f),
                    fmaxf(x0.z + v[2], 0.f), fmaxf(x0.w + v[3], 0.f));
                *(float4*)&op[tx * 4 + GS] = make_float4(
                    fmaxf(x1.x + v[4], 0.f), fmaxf(x1.y + v[5], 0.f),
                    fmaxf(x1.z + v[6], 0.f), fmaxf(x1.w + v[7], 0.f));
            } else if constexpr (MODE == MFFN) {
                const float* zr = g_z1 + (size_t)rg * DD;
                float*       op = g_o2 + (size_t)rg * DD;
                const float4 z0 = *(const float4*)&zr[tx * 4];
                const float4 z1 = *(const float4*)&zr[tx * 4 + GS];
                *(float4*)&op[tx * 4] = make_float4(
                    fmaxf(z0.x + v[0], 0.f), fmaxf(z0.y + v[1], 0.f),
                    fmaxf(z0.z + v[2], 0.f), fmaxf(z0.w + v[3], 0.f));
                *(float4*)&op[tx * 4 + GS] = make_float4(
                    fmaxf(z1.x + v[4], 0.f), fmaxf(z1.y + v[5], 0.f),
                    fmaxf(z1.z + v[6], 0.f), fmaxf(z1.w + v[7], 0.f));
            } else { // MMERGE
                float* op = dOut + (size_t)rg * DD;
                *(float4*)&op[tx * 4] = make_float4(
                    fmaxf(v[0], 0.f), fmaxf(v[1], 0.f), fmaxf(v[2], 0.f), fmaxf(v[3], 0.f));
                *(float4*)&op[tx * 4 + GS] = make_float4(
                    fmaxf(v[4], 0.f), fmaxf(v[5], 0.f), fmaxf(v[6], 0.f), fmaxf(v[7], 0.f));
            }
        }
    }
}

// =============================================================================
// Windowed attention: 1 warp per (window, head). WS=4, A=64.
// Only window index 63 within each (b,m) carries the shift mask (-100 cross).
// =============================================================================
__global__ void __launch_bounds__(256) attn_k() {
    const int task = blockIdx.x * 8 + (threadIdx.x >> 5);  // 65536 tasks
    const int lane = threadIdx.x & 31;
    const int w = task >> 2, h = task & 3;
    const size_t base = (size_t)(w << 2) * HA + (h << 6) + lane;

    float q0[4], q1[4], k0v[4], k1v[4], v0[4], v1[4];
    #pragma unroll
    for (int r = 0; r < 4; r++) {
        q0[r]  = g_Q[base + (size_t)r * HA];  q1[r]  = g_Q[base + (size_t)r * HA + 32];
        k0v[r] = g_K[base + (size_t)r * HA];  k1v[r] = g_K[base + (size_t)r * HA + 32];
        v0[r]  = g_V[base + (size_t)r * HA];  v1[r]  = g_V[base + (size_t)r * HA + 32];
    }

    float s[4][4];
    #pragma unroll
    for (int r = 0; r < 4; r++)
        #pragma unroll
        for (int c = 0; c < 4; c++) {
            float p = q0[r] * k0v[c] + q1[r] * k1v[c];
            #pragma unroll
            for (int m = 16; m >= 1; m >>= 1) p += __shfl_xor_sync(0xffffffffu, p, m);
            s[r][c] = p * 0.125f;  // 1/sqrt(64)
        }

    if ((w & 63) == 63) {
        #pragma unroll
        for (int r = 0; r < 4; r++)
            #pragma unroll
            for (int c = 0; c < 4; c++)
                if ((r < 2) != (c < 2)) s[r][c] -= 100.0f;
    }

    #pragma unroll
    for (int r = 0; r < 4; r++) {
        const float m = fmaxf(fmaxf(s[r][0], s[r][1]), fmaxf(s[r][2], s[r][3]));
        const float e0 = expf(s[r][0] - m), e1 = expf(s[r][1] - m);
        const float e2 = expf(s[r][2] - m), e3 = expf(s[r][3] - m);
        const float inv = 1.0f / (e0 + e1 + e2 + e3);
        g_Z[base + (size_t)r * HA]      = (e0 * v0[0] + e1 * v0[1] + e2 * v0[2] + e3 * v0[3]) * inv;
        g_Z[base + (size_t)r * HA + 32] = (e0 * v1[0] + e1 * v1[1] + e2 * v1[2] + e3 * v1[3]) * inv;
    }
}

// =============================================================================
extern "C" void kernel_launch(void* const* d_in, const int* in_sizes, int n_in,
                              void* d_out, int out_size) {
    (void)in_sizes; (void)n_in; (void)out_size;
    const float* x     = (const float*)d_in[0];
    const float* Wq    = (const float*)d_in[1];
    const float* bq    = (const float*)d_in[2];
    const float* Wk    = (const float*)d_in[3];
    const float* bk    = (const float*)d_in[4];
    const float* Wv    = (const float*)d_in[5];
    const float* bv    = (const float*)d_in[6];
    const float* aW    = (const float*)d_in[7];
    const float* ab    = (const float*)d_in[8];
    const float* ag    = (const float*)d_in[9];
    const float* abeta = (const float*)d_in[10];
    const float* fW    = (const float*)d_in[11];
    const float* fb    = (const float*)d_in[12];
    const float* fg    = (const float*)d_in[13];
    const float* fbeta = (const float*)d_in[14];
    const float* dW    = (const float*)d_in[15];
    const float* db    = (const float*)d_in[16];
    const float* dg    = (const float*)d_in[17];
    const float* dbeta = (const float*)d_in[18];
    float* out = (float*)d_out;

    // 1) QKV projections on shifted tokens (grid.y selects Wq/Wk/Wv)
    gemm_k<MQKV, 256, 512, 64><<<dim3(TOKS / 64, 3, 1), 256>>>(
        x, Wq, bq, Wk, bk, Wv, bv, nullptr, nullptr, nullptr);

    // 2) windowed attention -> g_Z
    attn_k<<<TOKS * 4 / (4 * 8), 256>>>();

    // 3) attn proj + LN + reverse shift + relu(x + .) -> g_z1
    gemm_k<MPROJ, 512, 256, 32><<<TOKS / 32, 256>>>(
        x, aW, ab, nullptr, nullptr, nullptr, nullptr, ag, abeta, nullptr);

    // 4) FFN + LN + relu(z1 + .) -> g_o2
    gemm_k<MFFN, 512, 512, 32><<<TOKS / 32, 256>>>(
        nullptr, fW, fb, nullptr, nullptr, nullptr, nullptr, fg, fbeta, nullptr);

    // 5) patch merge (K=1024 concat gather) + LN + relu -> d_out
    gemm_k<MMERGE, 512, 1024, 32><<<(TOKS / 2) / 32, 256>>>(
        nullptr, dW, db, nullptr, nullptr, nullptr, nullptr, dg, dbeta, out);
}

// round 5
// speedup vs baseline: 4.1128x; 2.9548x over previous
#include <cuda_runtime.h>
#include <cuda_bf16.h>
#include <math.h>
#include <stdint.h>

// Problem constants
#define PP   256        // patches per (b,m)
#define DD   512        // model dim
#define HA   256        // H*A
#define TOKS 65536      // B*M*P

enum { MQKV = 0, MPROJ = 1, MFFN = 2, MMERGE = 3 };

// ---------------- scratch (device globals; allocation-free rule) -------------
__device__ float g_Q[(size_t)TOKS * HA];
__device__ float g_K[(size_t)TOKS * HA];
__device__ float g_V[(size_t)TOKS * HA];
__device__ float g_Z[(size_t)TOKS * HA];
__device__ float g_z1[(size_t)TOKS * DD];
__device__ float g_o2[(size_t)TOKS * DD];
__device__ float g_S[(size_t)TOKS * DD];      // raw GEMM output (pre-LN)
// packed split-bf16 weights: per mat [kchunk(32)][split(hi/lo)][n][4 x 16B units,
// unit ku stored at slot ku ^ ((n>>1)&3)]  -> 4*K*N bytes per mat, 5MB total
__device__ __align__(16) unsigned char g_Wpack[5u << 20];

// ---------------- helpers ----------------------------------------------------
__device__ __forceinline__ uint32_t smem_to_u32(const void* p) {
    uint32_t a;
    asm("{ .reg .u64 t; cvta.to.shared.u64 t, %1; cvt.u32.u64 %0, t; }" : "=r"(a) : "l"(p));
    return a;
}
__device__ __forceinline__ void cp16(uint32_t saddr, const void* g) {
    asm volatile("cp.async.cg.shared.global [%0], [%1], 16;" :: "r"(saddr), "l"(g));
}
__device__ __forceinline__ void cp_commit() { asm volatile("cp.async.commit_group;"); }
__device__ __forceinline__ void cp_wait0()  { asm volatile("cp.async.wait_group 0;" ::: "memory"); }

__device__ __forceinline__ void ldm4(uint32_t* d, uint32_t addr) {
    asm volatile("ldmatrix.sync.aligned.m8n8.x4.shared.b16 {%0,%1,%2,%3}, [%4];"
        : "=r"(d[0]), "=r"(d[1]), "=r"(d[2]), "=r"(d[3]) : "r"(addr));
}
__device__ __forceinline__ void mma16816(float* c, const uint32_t* a, uint32_t b0, uint32_t b1) {
    asm volatile("mma.sync.aligned.m16n8k16.row.col.f32.bf16.bf16.f32 "
        "{%0,%1,%2,%3}, {%4,%5,%6,%7}, {%8,%9}, {%0,%1,%2,%3};"
        : "+f"(c[0]), "+f"(c[1]), "+f"(c[2]), "+f"(c[3])
        : "r"(a[0]), "r"(a[1]), "r"(a[2]), "r"(a[3]), "r"(b0), "r"(b1));
}

__device__ __forceinline__ void split8(const float4 a, const float4 b, uint4& H, uint4& L) {
    const float f[8] = {a.x, a.y, a.z, a.w, b.x, b.y, b.z, b.w};
    uint32_t hw[4], lw[4];
    #pragma unroll
    for (int i = 0; i < 4; i++) {
        const float x0 = f[2 * i], x1 = f[2 * i + 1];
        const __nv_bfloat16 h0 = __float2bfloat16(x0), h1 = __float2bfloat16(x1);
        const __nv_bfloat16 l0 = __float2bfloat16(x0 - __bfloat162float(h0));
        const __nv_bfloat16 l1 = __float2bfloat16(x1 - __bfloat162float(h1));
        hw[i] = (uint32_t)__bfloat16_as_ushort(h0) | ((uint32_t)__bfloat16_as_ushort(h1) << 16);
        lw[i] = (uint32_t)__bfloat16_as_ushort(l0) | ((uint32_t)__bfloat16_as_ushort(l1) << 16);
    }
    H = make_uint4(hw[0], hw[1], hw[2], hw[3]);
    L = make_uint4(lw[0], lw[1], lw[2], lw[3]);
}

// =============================================================================
// Weight pre-pack: fp32 W[N][K] -> split bf16 chunks ready for cp.async.
// unit = 16B (8 bf16). dst unit = seg + ((c*2+split)*N + n)*4 + (ku ^ ((n>>1)&3))
// =============================================================================
__global__ void pack_w_k(const float* __restrict__ Wq, const float* __restrict__ Wk,
                         const float* __restrict__ Wv, const float* __restrict__ aW,
                         const float* __restrict__ fW, const float* __restrict__ dW) {
    const int u = blockIdx.x * 256 + threadIdx.x;   // logical unit, 327680 total
    const float* W; int N, K, seg;
    if      (u < 32768)  { W = Wq; N = 256; K = 512;  seg = 0; }
    else if (u < 65536)  { W = Wk; N = 256; K = 512;  seg = 32768; }
    else if (u < 98304)  { W = Wv; N = 256; K = 512;  seg = 65536; }
    else if (u < 131072) { W = aW; N = 512; K = 256;  seg = 98304; }
    else if (u < 196608) { W = fW; N = 512; K = 512;  seg = 131072; }
    else                 { W = dW; N = 512; K = 1024; seg = 196608; }
    const int lu = u - seg;
    const int c     = lu / (8 * N);
    const int rem   = lu % (8 * N);
    const int split = rem / (4 * N);
    const int rem2  = rem % (4 * N);
    const int n  = rem2 >> 2, ku = rem2 & 3;
    const float* src = W + (size_t)n * K + c * 32 + ku * 8;
    const float4 a = *(const float4*)src;
    const float4 b = *(const float4*)(src + 4);
    uint4 H, L;
    split8(a, b, H, L);
    const size_t dst = ((size_t)seg + ((size_t)(c * 2 + split) * N + n) * 4 + (ku ^ ((n >> 1) & 3))) * 16;
    *(uint4*)(g_Wpack + dst) = (split == 0) ? H : L;
}

// =============================================================================
// Tensor-core GEMM via mma.sync (bf16 3-term split). CTA tile 128x128, KC=32.
// 8 warps: warp grid 2(m) x 4(n), warp tile 64x32 = 4 m16-tiles x 4 n8-tiles.
// =============================================================================
template<int MODE, int K>
__global__ void __launch_bounds__(256, 2) gemm_mma(
    const float* __restrict__ Ax,
    const float* __restrict__ b0, const float* __restrict__ b1,
    const float* __restrict__ b2, size_t wofs)
{
    constexpr int CH = K / 32;
    constexpr int NMAT = (MODE == MQKV) ? 256 : 512;
    constexpr uint32_t SA = 0, SB = 32768, SBIAS = 65536;

    extern __shared__ __align__(16) unsigned char smem[];
    const uint32_t sb = smem_to_u32(smem);
    const int tid = threadIdx.x, lane = tid & 31, w = tid >> 5;
    const int wm = w >> 2, wn = w & 3;
    const int bx = blockIdx.x, nb = blockIdx.y;

    size_t wseg = wofs;
    int nloc0;
    const float* Bias;
    float* Obuf;
    if constexpr (MODE == MQKV) {
        const int mat = nb >> 1;
        wseg += (size_t)mat * (512u << 10);
        nloc0 = (nb & 1) * 128;
        Bias = (mat == 0) ? b0 : (mat == 1) ? b1 : b2;
        Obuf = (mat == 0) ? g_Q : (mat == 1) ? g_K : g_V;
    } else {
        nloc0 = nb * 128;
        Bias = b0;
        Obuf = g_S;
    }
    if (tid < 128) ((float*)(smem + SBIAS))[tid] = Bias[nloc0 + tid];

    // ---- A staging identity: thread -> (row r, half hh) : 16 fp32 per chunk
    const int r = tid >> 1, hh = tid & 1;
    const int rgl = bx * 128 + r;
    const float* arow = nullptr;
    int mtok = 0;
    if constexpr (MODE == MQKV) {
        const int srow = (rgl & ~(PP - 1)) | ((rgl + 2) & (PP - 1));   // roll(x,-2)
        arow = Ax + (size_t)srow * DD;
    } else if constexpr (MODE == MPROJ) {
        arow = g_Z + (size_t)rgl * HA;
    } else if constexpr (MODE == MFFN) {
        arow = g_z1 + (size_t)rgl * DD;
    } else {
        mtok = ((rgl >> 7) << 8) + ((rgl & 127) << 1);
    }

    // ---- ldmatrix per-thread address components
    const int am = lane >> 3, atr = lane & 7;
    int aRow[4], aSw[4], bRow[2], bSw[2];
    #pragma unroll
    for (int i = 0; i < 4; i++) {
        const int row = wm * 64 + i * 16 + (am & 1) * 8 + atr;
        aRow[i] = row * 64; aSw[i] = (row >> 1) & 3;
    }
    #pragma unroll
    for (int p = 0; p < 2; p++) {
        const int n = wn * 32 + p * 16 + (am >> 1) * 8 + atr;
        bRow[p] = n * 64; bSw[p] = (n >> 1) & 3;
    }
    const int akb = am >> 1;   // A k-unit bit
    const int bkb = am & 1;    // B k-unit bit

    float acc[4][4][4];
    #pragma unroll
    for (int i = 0; i < 4; i++)
        #pragma unroll
        for (int j = 0; j < 4; j++)
            #pragma unroll
            for (int e = 0; e < 4; e++) acc[i][j][e] = 0.f;

    float4 av[4];
    auto ldgA = [&](int c) {
        const float* ap;
        if constexpr (MODE == MMERGE)
            ap = g_o2 + (size_t)(mtok + (c >> 4)) * DD + ((c & 15) * 32 + hh * 16);
        else
            ap = arow + c * 32 + hh * 16;
        #pragma unroll
        for (int i = 0; i < 4; i++) av[i] = __ldg((const float4*)(ap + i * 4));
    };
    auto stsA = [&](int buf) {
        #pragma unroll
        for (int g = 0; g < 2; g++) {
            uint4 H, L;
            split8(av[2 * g], av[2 * g + 1], H, L);
            const int su = (hh * 2 + g) ^ ((r >> 1) & 3);
            *(uint4*)(smem + SA + buf * 16384 +        r * 64 + su * 16) = H;
            *(uint4*)(smem + SA + buf * 16384 + 8192 + r * 64 + su * 16) = L;
        }
    };
    auto cpB = [&](int c, int buf) {
        #pragma unroll
        for (int k = 0; k < 4; k++) {
            const int i = tid + k * 256;           // 0..1023 units
            const int s = i >> 9, rs = i & 511;
            cp16(sb + SB + buf * 16384 + s * 8192 + rs * 16,
                 g_Wpack + wseg + (((size_t)(c * 2 + s) * NMAT + nloc0) << 6) + ((size_t)rs << 4));
        }
        cp_commit();
    };
    auto compute = [&](int buf) {
        const uint32_t ab0 = sb + SA + buf * 16384;
        const uint32_t bb0 = sb + SB + buf * 16384;
        #pragma unroll
        for (int ks = 0; ks < 2; ks++) {
            uint32_t ah[4][4], bh[2][4], t4[4];
            const int kua = ks * 2 + akb, kub = ks * 2 + bkb;
            #pragma unroll
            for (int i = 0; i < 4; i++) ldm4(ah[i], ab0 + aRow[i] + ((kua ^ aSw[i]) << 4));
            #pragma unroll
            for (int p = 0; p < 2; p++) ldm4(bh[p], bb0 + bRow[p] + ((kub ^ bSw[p]) << 4));
            // hi * hi
            #pragma unroll
            for (int i = 0; i < 4; i++)
                #pragma unroll
                for (int j = 0; j < 4; j++)
                    mma16816(acc[i][j], ah[i], bh[j >> 1][(j & 1) * 2], bh[j >> 1][(j & 1) * 2 + 1]);
            // lo * hi  (A_lo from split-1 half of A smem)
            #pragma unroll
            for (int i = 0; i < 4; i++) {
                ldm4(t4, ab0 + 8192 + aRow[i] + ((kua ^ aSw[i]) << 4));
                #pragma unroll
                for (int j = 0; j < 4; j++)
                    mma16816(acc[i][j], t4, bh[j >> 1][(j & 1) * 2], bh[j >> 1][(j & 1) * 2 + 1]);
            }
            // hi * lo  (B_lo from split-1 half of B smem)
            #pragma unroll
            for (int p = 0; p < 2; p++) {
                ldm4(t4, bb0 + 8192 + bRow[p] + ((kub ^ bSw[p]) << 4));
                #pragma unroll
                for (int i = 0; i < 4; i++) {
                    mma16816(acc[i][2 * p],     ah[i], t4[0], t4[1]);
                    mma16816(acc[i][2 * p + 1], ah[i], t4[2], t4[3]);
                }
            }
        }
    };

    // ---- pipeline
    ldgA(0);
    cpB(0, 0);
    stsA(0);
    cp_wait0();
    __syncthreads();
    int buf = 0;
    for (int c = 0; c < CH; c++) {
        if (c + 1 < CH) { ldgA(c + 1); cpB(c + 1, buf ^ 1); }
        compute(buf);
        if (c + 1 < CH) { stsA(buf ^ 1); cp_wait0(); }
        __syncthreads();
        buf ^= 1;
    }

    // ---- epilogue: bias + store fp32
    const float* sBias = (const float*)(smem + SBIAS);
    #pragma unroll
    for (int i = 0; i < 4; i++) {
        const int row0 = bx * 128 + wm * 64 + i * 16 + (lane >> 2);
        #pragma unroll
        for (int j = 0; j < 4; j++) {
            const int cl = wn * 32 + j * 8 + 2 * (lane & 3);
            const float bb0 = sBias[cl], bb1 = sBias[cl + 1];
            float* p0;
            int stride;
            if constexpr (MODE == MQKV) {
                p0 = Obuf + (size_t)row0 * 256 + (nb & 1) * 128 + cl;
                stride = 8 * 256;
            } else {
                p0 = Obuf + (size_t)row0 * 512 + nloc0 + cl;
                stride = 8 * 512;
            }
            *(float2*)p0            = make_float2(acc[i][j][0] + bb0, acc[i][j][1] + bb1);
            *(float2*)(p0 + stride) = make_float2(acc[i][j][2] + bb0, acc[i][j][3] + bb1);
        }
    }
}

// =============================================================================
// Fused LayerNorm passes (128 threads per row of 512)
// MODE 0: g_z1[dtok] = relu(x[dtok] + LN(g_S[row]))   (reverse shift +2)
// MODE 1: g_o2[row]  = relu(g_z1[row] + LN(g_S[row]))
// MODE 2: Out[row]   = relu(LN(g_S[row]))
// =============================================================================
template<int MODE>
__global__ void __launch_bounds__(128) ln_k(const float* __restrict__ X,
                                            const float* __restrict__ gamma,
                                            const float* __restrict__ beta,
                                            float* __restrict__ Out)
{
    const int row = blockIdx.x, tid = threadIdx.x;
    const int lane = tid & 31, wid = tid >> 5;
    const float4 v = *(const float4*)(g_S + (size_t)row * DD + tid * 4);
    float s = v.x + v.y + v.z + v.w;
    float q = v.x * v.x + v.y * v.y + v.z * v.z + v.w * v.w;
    #pragma unroll
    for (int m = 16; m >= 1; m >>= 1) {
        s += __shfl_xor_sync(0xffffffffu, s, m);
        q += __shfl_xor_sync(0xffffffffu, q, m);
    }
    __shared__ float2 red[4];
    if (lane == 0) red[wid] = make_float2(s, q);
    __syncthreads();
    float S = 0.f, Q = 0.f;
    #pragma unroll
    for (int k = 0; k < 4; k++) { S += red[k].x; Q += red[k].y; }
    const float mu = S * (1.0f / DD);
    const float var = Q * (1.0f / DD) - mu * mu;
    const float rs = rsqrtf(var + 1e-5f);
    const float4 g = *(const float4*)(gamma + tid * 4);
    const float4 b = *(const float4*)(beta + tid * 4);
    float4 o = make_float4((v.x - mu) * rs * g.x + b.x, (v.y - mu) * rs * g.y + b.y,
                           (v.z - mu) * rs * g.z + b.z, (v.w - mu) * rs * g.w + b.w);
    if constexpr (MODE == 0) {
        const int dtok = (row & ~(PP - 1)) | ((row + 2) & (PP - 1));
        const float4 xr = *(const float4*)(X + (size_t)dtok * DD + tid * 4);
        *(float4*)(g_z1 + (size_t)dtok * DD + tid * 4) = make_float4(
            fmaxf(xr.x + o.x, 0.f), fmaxf(xr.y + o.y, 0.f),
            fmaxf(xr.z + o.z, 0.f), fmaxf(xr.w + o.w, 0.f));
    } else if constexpr (MODE == 1) {
        const float4 zr = *(const float4*)(g_z1 + (size_t)row * DD + tid * 4);
        *(float4*)(g_o2 + (size_t)row * DD + tid * 4) = make_float4(
            fmaxf(zr.x + o.x, 0.f), fmaxf(zr.y + o.y, 0.f),
            fmaxf(zr.z + o.z, 0.f), fmaxf(zr.w + o.w, 0.f));
    } else {
        *(float4*)(Out + (size_t)row * DD + tid * 4) = make_float4(
            fmaxf(o.x, 0.f), fmaxf(o.y, 0.f), fmaxf(o.z, 0.f), fmaxf(o.w, 0.f));
    }
}

// =============================================================================
// Windowed attention: 1 warp per (window, head). WS=4, A=64.
// =============================================================================
__global__ void __launch_bounds__(256) attn_k() {
    const int task = blockIdx.x * 8 + (threadIdx.x >> 5);
    const int lane = threadIdx.x & 31;
    const int w = task >> 2, h = task & 3;
    const size_t base = (size_t)(w << 2) * HA + (h << 6) + lane;

    float q0[4], q1[4], k0v[4], k1v[4], v0[4], v1[4];
    #pragma unroll
    for (int r = 0; r < 4; r++) {
        q0[r]  = g_Q[base + (size_t)r * HA];  q1[r]  = g_Q[base + (size_t)r * HA + 32];
        k0v[r] = g_K[base + (size_t)r * HA];  k1v[r] = g_K[base + (size_t)r * HA + 32];
        v0[r]  = g_V[base + (size_t)r * HA];  v1[r]  = g_V[base + (size_t)r * HA + 32];
    }
    float s[4][4];
    #pragma unroll
    for (int r = 0; r < 4; r++)
        #pragma unroll
        for (int c = 0; c < 4; c++) {
            float p = q0[r] * k0v[c] + q1[r] * k1v[c];
            #pragma unroll
            for (int m = 16; m >= 1; m >>= 1) p += __shfl_xor_sync(0xffffffffu, p, m);
            s[r][c] = p * 0.125f;
        }
    if ((w & 63) == 63) {
        #pragma unroll
        for (int r = 0; r < 4; r++)
            #pragma unroll
            for (int c = 0; c < 4; c++)
                if ((r < 2) != (c < 2)) s[r][c] -= 100.0f;
    }
    #pragma unroll
    for (int r = 0; r < 4; r++) {
        const float m = fmaxf(fmaxf(s[r][0], s[r][1]), fmaxf(s[r][2], s[r][3]));
        const float e0 = expf(s[r][0] - m), e1 = expf(s[r][1] - m);
        const float e2 = expf(s[r][2] - m), e3 = expf(s[r][3] - m);
        const float inv = 1.0f / (e0 + e1 + e2 + e3);
        g_Z[base + (size_t)r * HA]      = (e0 * v0[0] + e1 * v0[1] + e2 * v0[2] + e3 * v0[3]) * inv;
        g_Z[base + (size_t)r * HA + 32] = (e0 * v1[0] + e1 * v1[1] + e2 * v1[2] + e3 * v1[3]) * inv;
    }
}

// =============================================================================
#define GEMM_SMEM (65536 + 512)

extern "C" void kernel_launch(void* const* d_in, const int* in_sizes, int n_in,
                              void* d_out, int out_size) {
    (void)in_sizes; (void)n_in; (void)out_size;
    const float* x     = (const float*)d_in[0];
    const float* Wq    = (const float*)d_in[1];
    const float* bq    = (const float*)d_in[2];
    const float* Wk    = (const float*)d_in[3];
    const float* bk    = (const float*)d_in[4];
    const float* Wv    = (const float*)d_in[5];
    const float* bv    = (const float*)d_in[6];
    const float* aW    = (const float*)d_in[7];
    const float* ab    = (const float*)d_in[8];
    const float* ag    = (const float*)d_in[9];
    const float* abeta = (const float*)d_in[10];
    const float* fW    = (const float*)d_in[11];
    const float* fb    = (const float*)d_in[12];
    const float* fg    = (const float*)d_in[13];
    const float* fbeta = (const float*)d_in[14];
    const float* dW    = (const float*)d_in[15];
    const float* db    = (const float*)d_in[16];
    const float* dg    = (const float*)d_in[17];
    const float* dbeta = (const float*)d_in[18];
    float* out = (float*)d_out;

    cudaFuncSetAttribute(gemm_mma<MQKV, 512>,   cudaFuncAttributeMaxDynamicSharedMemorySize, GEMM_SMEM);
    cudaFuncSetAttribute(gemm_mma<MPROJ, 256>,  cudaFuncAttributeMaxDynamicSharedMemorySize, GEMM_SMEM);
    cudaFuncSetAttribute(gemm_mma<MFFN, 512>,   cudaFuncAttributeMaxDynamicSharedMemorySize, GEMM_SMEM);
    cudaFuncSetAttribute(gemm_mma<MMERGE, 1024>, cudaFuncAttributeMaxDynamicSharedMemorySize, GEMM_SMEM);

    // 0) pre-split/pre-swizzle weights
    pack_w_k<<<1280, 256>>>(Wq, Wk, Wv, aW, fW, dW);

    // 1) QKV on shifted tokens -> g_Q/g_K/g_V (bias included)
    gemm_mma<MQKV, 512><<<dim3(TOKS / 128, 6, 1), 256, GEMM_SMEM>>>(
        x, bq, bk, bv, 0ull);

    // 2) windowed attention -> g_Z
    attn_k<<<8192, 256>>>();

    // 3) attn proj -> g_S ; LN + reverse shift + relu(x + .) -> g_z1
    gemm_mma<MPROJ, 256><<<dim3(TOKS / 128, 4, 1), 256, GEMM_SMEM>>>(
        nullptr, ab, nullptr, nullptr, 98304ull * 16);
    ln_k<0><<<TOKS, 128>>>(x, ag, abeta, nullptr);

    // 4) FFN -> g_S ; LN + relu(z1 + .) -> g_o2
    gemm_mma<MFFN, 512><<<dim3(TOKS / 128, 4, 1), 256, GEMM_SMEM>>>(
        nullptr, fb, nullptr, nullptr, 131072ull * 16);
    ln_k<1><<<TOKS, 128>>>(nullptr, fg, fbeta, nullptr);

    // 5) patch merge -> g_S ; LN + relu -> out
    gemm_mma<MMERGE, 1024><<<dim3(TOKS / 256, 4, 1), 256, GEMM_SMEM>>>(
        nullptr, db, nullptr, nullptr, 196608ull * 16);
    ln_k<2><<<TOKS / 2, 128>>>(nullptr, dg, dbeta, out);
}

// round 8
// speedup vs baseline: 5.3664x; 1.3048x over previous
#include <cuda_runtime.h>
#include <cuda_fp16.h>
#include <math.h>
#include <stdint.h>

// Problem constants
#define PP   256        // patches per (b,m)
#define DD   512        // model dim
#define HA   256        // H*A
#define TOKS 65536      // B*M*P

enum { MQKV = 0, MPROJ = 1, MFFN = 2, MMERGE = 3 };

// ---------------- scratch (device globals; allocation-free rule) -------------
__device__ float g_Q[(size_t)TOKS * HA];
__device__ float g_K[(size_t)TOKS * HA];
__device__ float g_V[(size_t)TOKS * HA];
__device__ float g_Z[(size_t)TOKS * HA];
__device__ float g_z1[(size_t)TOKS * DD];
__device__ float g_o2[(size_t)TOKS * DD];
__device__ float g_S[(size_t)TOKS * DD];      // raw GEMM output (pre-LN)
// packed split-fp16 weights: per mat [kchunk(32)][split(hi/lo)][n][4 x 16B units,
// unit ku stored at slot ku ^ ((n>>1)&3)]  -> 4*K*N bytes per mat, 5MB total
__device__ __align__(16) unsigned char g_Wpack[5u << 20];

// ---------------- helpers ----------------------------------------------------
__device__ __forceinline__ uint32_t smem_to_u32(const void* p) {
    uint32_t a;
    asm("{ .reg .u64 t; cvta.to.shared.u64 t, %1; cvt.u32.u64 %0, t; }" : "=r"(a) : "l"(p));
    return a;
}
__device__ __forceinline__ void cp16(uint32_t saddr, const void* g) {
    asm volatile("cp.async.cg.shared.global [%0], [%1], 16;" :: "r"(saddr), "l"(g));
}
__device__ __forceinline__ void cp_commit() { asm volatile("cp.async.commit_group;"); }
__device__ __forceinline__ void cp_wait0()  { asm volatile("cp.async.wait_group 0;" ::: "memory"); }

__device__ __forceinline__ void ldm4(uint32_t* d, uint32_t addr) {
    asm volatile("ldmatrix.sync.aligned.m8n8.x4.shared.b16 {%0,%1,%2,%3}, [%4];"
        : "=r"(d[0]), "=r"(d[1]), "=r"(d[2]), "=r"(d[3]) : "r"(addr));
}
__device__ __forceinline__ void mma16816(float* c, const uint32_t* a, uint32_t b0, uint32_t b1) {
    asm volatile("mma.sync.aligned.m16n8k16.row.col.f32.f16.f16.f32 "
        "{%0,%1,%2,%3}, {%4,%5,%6,%7}, {%8,%9}, {%0,%1,%2,%3};"
        : "+f"(c[0]), "+f"(c[1]), "+f"(c[2]), "+f"(c[3])
        : "r"(a[0]), "r"(a[1]), "r"(a[2]), "r"(a[3]), "r"(b0), "r"(b1));
}

// 8 fp32 -> 8 fp16 (one 16B unit)
__device__ __forceinline__ uint4 cvt8h(const float4 a, const float4 b) {
    const float f[8] = {a.x, a.y, a.z, a.w, b.x, b.y, b.z, b.w};
    uint32_t w[4];
    #pragma unroll
    for (int i = 0; i < 4; i++) {
        const __half h0 = __float2half_rn(f[2 * i]);
        const __half h1 = __float2half_rn(f[2 * i + 1]);
        w[i] = (uint32_t)__half_as_ushort(h0) | ((uint32_t)__half_as_ushort(h1) << 16);
    }
    return make_uint4(w[0], w[1], w[2], w[3]);
}
// 8 fp32 -> split hi/lo fp16 units
__device__ __forceinline__ void split8h(const float4 a, const float4 b, uint4& H, uint4& L) {
    const float f[8] = {a.x, a.y, a.z, a.w, b.x, b.y, b.z, b.w};
    uint32_t hw[4], lw[4];
    #pragma unroll
    for (int i = 0; i < 4; i++) {
        const float x0 = f[2 * i], x1 = f[2 * i + 1];
        const __half h0 = __float2half_rn(x0), h1 = __float2half_rn(x1);
        const __half l0 = __float2half_rn(x0 - __half2float(h0));
        const __half l1 = __float2half_rn(x1 - __half2float(h1));
        hw[i] = (uint32_t)__half_as_ushort(h0) | ((uint32_t)__half_as_ushort(h1) << 16);
        lw[i] = (uint32_t)__half_as_ushort(l0) | ((uint32_t)__half_as_ushort(l1) << 16);
    }
    H = make_uint4(hw[0], hw[1], hw[2], hw[3]);
    L = make_uint4(lw[0], lw[1], lw[2], lw[3]);
}

// =============================================================================
// Weight pre-pack: fp32 W[N][K] -> split fp16 chunks ready for cp.async.
// unit = 16B (8 fp16). dst unit = seg + ((c*2+split)*N + n)*4 + (ku ^ ((n>>1)&3))
// =============================================================================
__global__ void pack_w_k(const float* __restrict__ Wq, const float* __restrict__ Wk,
                         const float* __restrict__ Wv, const float* __restrict__ aW,
                         const float* __restrict__ fW, const float* __restrict__ dW) {
    const int u = blockIdx.x * 256 + threadIdx.x;   // logical unit, 327680 total
    const float* W; int N, K, seg;
    if      (u < 32768)  { W = Wq; N = 256; K = 512;  seg = 0; }
    else if (u < 65536)  { W = Wk; N = 256; K = 512;  seg = 32768; }
    else if (u < 98304)  { W = Wv; N = 256; K = 512;  seg = 65536; }
    else if (u < 131072) { W = aW; N = 512; K = 256;  seg = 98304; }
    else if (u < 196608) { W = fW; N = 512; K = 512;  seg = 131072; }
    else                 { W = dW; N = 512; K = 1024; seg = 196608; }
    const int lu = u - seg;
    const int c     = lu / (8 * N);
    const int rem   = lu % (8 * N);
    const int split = rem / (4 * N);
    const int rem2  = rem % (4 * N);
    const int n  = rem2 >> 2, ku = rem2 & 3;
    const float* src = W + (size_t)n * K + c * 32 + ku * 8;
    const float4 a = *(const float4*)src;
    const float4 b = *(const float4*)(src + 4);
    uint4 H, L;
    split8h(a, b, H, L);
    const size_t dst = ((size_t)seg + ((size_t)(c * 2 + split) * N + n) * 4 + (ku ^ ((n >> 1) & 3))) * 16;
    *(uint4*)(g_Wpack + dst) = (split == 0) ? H : L;
}

// =============================================================================
// Tensor-core GEMM via mma.sync, 2-term fp16 (A single, B = hi+lo split).
// CTA tile 128x128, KC=32, double-buffered. 8 warps: 2(m) x 4(n), warp 64x32.
// =============================================================================
template<int MODE, int K>
__global__ void __launch_bounds__(256, 2) gemm_mma(
    const float* __restrict__ Ax,
    const float* __restrict__ b0, const float* __restrict__ b1,
    const float* __restrict__ b2, size_t wofs)
{
    constexpr int CH = K / 32;
    constexpr int NMAT = (MODE == MQKV) ? 256 : 512;
    constexpr uint32_t SA = 0;          // [2][128 rows x 64B]        16KB
    constexpr uint32_t SB = 16384;      // [2][2 planes][128 x 64B]   32KB
    constexpr uint32_t SBIAS = 49152;

    extern __shared__ __align__(16) unsigned char smem[];
    const uint32_t sb = smem_to_u32(smem);
    const int tid = threadIdx.x, lane = tid & 31, w = tid >> 5;
    const int wm = w >> 2, wn = w & 3;
    const int bx = blockIdx.x, nb = blockIdx.y;

    size_t wseg = wofs;
    int nloc0;
    const float* Bias;
    float* Obuf;
    if constexpr (MODE == MQKV) {
        const int mat = nb >> 1;
        wseg += (size_t)mat * (512u << 10);
        nloc0 = (nb & 1) * 128;
        Bias = (mat == 0) ? b0 : (mat == 1) ? b1 : b2;
        Obuf = (mat == 0) ? g_Q : (mat == 1) ? g_K : g_V;
    } else {
        nloc0 = nb * 128;
        Bias = b0;
        Obuf = g_S;
    }
    if (tid < 128) ((float*)(smem + SBIAS))[tid] = Bias[nloc0 + tid];

    // ---- A staging identity: thread -> (row r, half hh) : 16 fp32 per chunk
    const int r = tid >> 1, hh = tid & 1;
    const int rgl = bx * 128 + r;
    const float* arow = nullptr;
    int mtok = 0;
    if constexpr (MODE == MQKV) {
        const int srow = (rgl & ~(PP - 1)) | ((rgl + 2) & (PP - 1));   // roll(x,-2)
        arow = Ax + (size_t)srow * DD;
    } else if constexpr (MODE == MPROJ) {
        arow = g_Z + (size_t)rgl * HA;
    } else if constexpr (MODE == MFFN) {
        arow = g_z1 + (size_t)rgl * DD;
    } else {
        mtok = ((rgl >> 7) << 8) + ((rgl & 127) << 1);
    }

    // ---- ldmatrix per-thread address components
    const int am = lane >> 3, atr = lane & 7;
    int aRow[4], aSw[4], bRow[2], bSw[2];
    #pragma unroll
    for (int i = 0; i < 4; i++) {
        const int row = wm * 64 + i * 16 + (am & 1) * 8 + atr;
        aRow[i] = row * 64; aSw[i] = (row >> 1) & 3;
    }
    #pragma unroll
    for (int p = 0; p < 2; p++) {
        const int n = wn * 32 + p * 16 + (am >> 1) * 8 + atr;
        bRow[p] = n * 64; bSw[p] = (n >> 1) & 3;
    }
    const int akb = am >> 1;   // A k-unit bit
    const int bkb = am & 1;    // B k-unit bit

    float acc[4][4][4];
    #pragma unroll
    for (int i = 0; i < 4; i++)
        #pragma unroll
        for (int j = 0; j < 4; j++)
            #pragma unroll
            for (int e = 0; e < 4; e++) acc[i][j][e] = 0.f;

    float4 av[4];
    auto ldgA = [&](int c) {
        const float* ap;
        if constexpr (MODE == MMERGE)
            ap = g_o2 + (size_t)(mtok + (c >> 4)) * DD + ((c & 15) * 32 + hh * 16);
        else
            ap = arow + c * 32 + hh * 16;
        #pragma unroll
        for (int i = 0; i < 4; i++) av[i] = __ldg((const float4*)(ap + i * 4));
    };
    auto stsA = [&](int buf) {
        #pragma unroll
        for (int g = 0; g < 2; g++) {
            const uint4 H = cvt8h(av[2 * g], av[2 * g + 1]);
            const int ku = hh * 2 + g;
            const int su = ku ^ ((r >> 1) & 3);
            *(uint4*)(smem + SA + buf * 8192 + r * 64 + su * 16) = H;
        }
    };
    auto cpB = [&](int c, int buf) {
        #pragma unroll
        for (int k = 0; k < 4; k++) {
            const int i = tid + k * 256;           // 0..1023 units (2 planes x 512)
            const int s = i >> 9, rs = i & 511;
            cp16(sb + SB + buf * 16384 + s * 8192 + rs * 16,
                 g_Wpack + wseg + (((size_t)(c * 2 + s) * NMAT + nloc0) << 6) + ((size_t)rs << 4));
        }
        cp_commit();
    };
    auto compute = [&](int buf) {
        const uint32_t ab0 = sb + SA + buf * 8192;
        const uint32_t bh0 = sb + SB + buf * 16384;
        const uint32_t bl0 = bh0 + 8192;
        #pragma unroll
        for (int ks = 0; ks < 2; ks++) {
            uint32_t ah[4][4], bh[2][4], bl[2][4];
            const int kua = ks * 2 + akb, kub = ks * 2 + bkb;
            #pragma unroll
            for (int i = 0; i < 4; i++) ldm4(ah[i], ab0 + aRow[i] + ((kua ^ aSw[i]) << 4));
            #pragma unroll
            for (int p = 0; p < 2; p++) {
                ldm4(bh[p], bh0 + bRow[p] + ((kub ^ bSw[p]) << 4));
                ldm4(bl[p], bl0 + bRow[p] + ((kub ^ bSw[p]) << 4));
            }
            #pragma unroll
            for (int i = 0; i < 4; i++)
                #pragma unroll
                for (int j = 0; j < 4; j++)
                    mma16816(acc[i][j], ah[i], bh[j >> 1][(j & 1) * 2], bh[j >> 1][(j & 1) * 2 + 1]);
            #pragma unroll
            for (int i = 0; i < 4; i++)
                #pragma unroll
                for (int j = 0; j < 4; j++)
                    mma16816(acc[i][j], ah[i], bl[j >> 1][(j & 1) * 2], bl[j >> 1][(j & 1) * 2 + 1]);
        }
    };

    // ---- pipeline
    ldgA(0);
    cpB(0, 0);
    stsA(0);
    cp_wait0();
    __syncthreads();
    int buf = 0;
    for (int c = 0; c < CH; c++) {
        if (c + 1 < CH) { ldgA(c + 1); cpB(c + 1, buf ^ 1); }
        compute(buf);
        if (c + 1 < CH) { stsA(buf ^ 1); cp_wait0(); }
        __syncthreads();
        buf ^= 1;
    }

    // ---- epilogue: bias + store fp32
    const float* sBias = (const float*)(smem + SBIAS);
    #pragma unroll
    for (int i = 0; i < 4; i++) {
        const int row0 = bx * 128 + wm * 64 + i * 16 + (lane >> 2);
        #pragma unroll
        for (int j = 0; j < 4; j++) {
            const int cl = wn * 32 + j * 8 + 2 * (lane & 3);
            const float bb0 = sBias[cl], bb1 = sBias[cl + 1];
            float* p0;
            int stride;
            if constexpr (MODE == MQKV) {
                p0 = Obuf + (size_t)row0 * 256 + (nb & 1) * 128 + cl;
                stride = 8 * 256;
            } else {
                p0 = Obuf + (size_t)row0 * 512 + nloc0 + cl;
                stride = 8 * 512;
            }
            *(float2*)p0            = make_float2(acc[i][j][0] + bb0, acc[i][j][1] + bb1);
            *(float2*)(p0 + stride) = make_float2(acc[i][j][2] + bb0, acc[i][j][3] + bb1);
        }
    }
}

// =============================================================================
// Fused LayerNorm passes (128 threads per row of 512)
// MODE 0: g_z1[dtok] = relu(x[dtok] + LN(g_S[row]))   (reverse shift +2)
// MODE 1: g_o2[row]  = relu(g_z1[row] + LN(g_S[row]))
// MODE 2: Out[row]   = relu(LN(g_S[row]))
// =============================================================================
template<int MODE>
__global__ void __launch_bounds__(128) ln_k(const float* __restrict__ X,
                                            const float* __restrict__ gamma,
                                            const float* __restrict__ beta,
                                            float* __restrict__ Out)
{
    const int row = blockIdx.x, tid = threadIdx.x;
    const int lane = tid & 31, wid = tid >> 5;
    const float4 v = *(const float4*)(g_S + (size_t)row * DD + tid * 4);
    float s = v.x + v.y + v.z + v.w;
    float q = v.x * v.x + v.y * v.y + v.z * v.z + v.w * v.w;
    #pragma unroll
    for (int m = 16; m >= 1; m >>= 1) {
        s += __shfl_xor_sync(0xffffffffu, s, m);
        q += __shfl_xor_sync(0xffffffffu, q, m);
    }
    __shared__ float2 red[4];
    if (lane == 0) red[wid] = make_float2(s, q);
    __syncthreads();
    float S = 0.f, Q = 0.f;
    #pragma unroll
    for (int k = 0; k < 4; k++) { S += red[k].x; Q += red[k].y; }
    const float mu = S * (1.0f / DD);
    const float var = Q * (1.0f / DD) - mu * mu;
    const float rs = rsqrtf(var + 1e-5f);
    const float4 g = *(const float4*)(gamma + tid * 4);
    const float4 b = *(const float4*)(beta + tid * 4);
    float4 o = make_float4((v.x - mu) * rs * g.x + b.x, (v.y - mu) * rs * g.y + b.y,
                           (v.z - mu) * rs * g.z + b.z, (v.w - mu) * rs * g.w + b.w);
    if constexpr (MODE == 0) {
        const int dtok = (row & ~(PP - 1)) | ((row + 2) & (PP - 1));
        const float4 xr = *(const float4*)(X + (size_t)dtok * DD + tid * 4);
        *(float4*)(g_z1 + (size_t)dtok * DD + tid * 4) = make_float4(
            fmaxf(xr.x + o.x, 0.f), fmaxf(xr.y + o.y, 0.f),
            fmaxf(xr.z + o.z, 0.f), fmaxf(xr.w + o.w, 0.f));
    } else if constexpr (MODE == 1) {
        const float4 zr = *(const float4*)(g_z1 + (size_t)row * DD + tid * 4);
        *(float4*)(g_o2 + (size_t)row * DD + tid * 4) = make_float4(
            fmaxf(zr.x + o.x, 0.f), fmaxf(zr.y + o.y, 0.f),
            fmaxf(zr.z + o.z, 0.f), fmaxf(zr.w + o.w, 0.f));
    } else {
        *(float4*)(Out + (size_t)row * DD + tid * 4) = make_float4(
            fmaxf(o.x, 0.f), fmaxf(o.y, 0.f), fmaxf(o.z, 0.f), fmaxf(o.w, 0.f));
    }
}

// =============================================================================
// Windowed attention: 1 warp per (window, head). WS=4, A=64.
// =============================================================================
__global__ void __launch_bounds__(256) attn_k() {
    const int task = blockIdx.x * 8 + (threadIdx.x >> 5);
    const int lane = threadIdx.x & 31;
    const int w = task >> 2, h = task & 3;
    const size_t base = (size_t)(w << 2) * HA + (h << 6) + lane;

    float q0[4], q1[4], k0v[4], k1v[4], v0[4], v1[4];
    #pragma unroll
    for (int r = 0; r < 4; r++) {
        q0[r]  = g_Q[base + (size_t)r * HA];  q1[r]  = g_Q[base + (size_t)r * HA + 32];
        k0v[r] = g_K[base + (size_t)r * HA];  k1v[r] = g_K[base + (size_t)r * HA + 32];
        v0[r]  = g_V[base + (size_t)r * HA];  v1[r]  = g_V[base + (size_t)r * HA + 32];
    }
    float s[4][4];
    #pragma unroll
    for (int r = 0; r < 4; r++)
        #pragma unroll
        for (int c = 0; c < 4; c++) {
            float p = q0[r] * k0v[c] + q1[r] * k1v[c];
            #pragma unroll
            for (int m = 16; m >= 1; m >>= 1) p += __shfl_xor_sync(0xffffffffu, p, m);
            s[r][c] = p * 0.125f;
        }
    if ((w & 63) == 63) {
        #pragma unroll
        for (int r = 0; r < 4; r++)
            #pragma unroll
            for (int c = 0; c < 4; c++)
                if ((r < 2) != (c < 2)) s[r][c] -= 100.0f;
    }
    #pragma unroll
    for (int r = 0; r < 4; r++) {
        const float m = fmaxf(fmaxf(s[r][0], s[r][1]), fmaxf(s[r][2], s[r][3]));
        const float e0 = expf(s[r][0] - m), e1 = expf(s[r][1] - m);
        const float e2 = expf(s[r][2] - m), e3 = expf(s[r][3] - m);
        const float inv = 1.0f / (e0 + e1 + e2 + e3);
        g_Z[base + (size_t)r * HA]      = (e0 * v0[0] + e1 * v0[1] + e2 * v0[2] + e3 * v0[3]) * inv;
        g_Z[base + (size_t)r * HA + 32] = (e0 * v1[0] + e1 * v1[1] + e2 * v1[2] + e3 * v1[3]) * inv;
    }
}

// =============================================================================
#define GEMM_SMEM (49152 + 512)

extern "C" void kernel_launch(void* const* d_in, const int* in_sizes, int n_in,
                              void* d_out, int out_size) {
    (void)in_sizes; (void)n_in; (void)out_size;
    const float* x     = (const float*)d_in[0];
    const float* Wq    = (const float*)d_in[1];
    const float* bq    = (const float*)d_in[2];
    const float* Wk    = (const float*)d_in[3];
    const float* bk    = (const float*)d_in[4];
    const float* Wv    = (const float*)d_in[5];
    const float* bv    = (const float*)d_in[6];
    const float* aW    = (const float*)d_in[7];
    const float* ab    = (const float*)d_in[8];
    const float* ag    = (const float*)d_in[9];
    const float* abeta = (const float*)d_in[10];
    const float* fW    = (const float*)d_in[11];
    const float* fb    = (const float*)d_in[12];
    const float* fg    = (const float*)d_in[13];
    const float* fbeta = (const float*)d_in[14];
    const float* dW    = (const float*)d_in[15];
    const float* db    = (const float*)d_in[16];
    const float* dg    = (const float*)d_in[17];
    const float* dbeta = (const float*)d_in[18];
    float* out = (float*)d_out;

    cudaFuncSetAttribute(gemm_mma<MQKV, 512>,   cudaFuncAttributeMaxDynamicSharedMemorySize, GEMM_SMEM);
    cudaFuncSetAttribute(gemm_mma<MPROJ, 256>,  cudaFuncAttributeMaxDynamicSharedMemorySize, GEMM_SMEM);
    cudaFuncSetAttribute(gemm_mma<MFFN, 512>,   cudaFuncAttributeMaxDynamicSharedMemorySize, GEMM_SMEM);
    cudaFuncSetAttribute(gemm_mma<MMERGE, 1024>, cudaFuncAttributeMaxDynamicSharedMemorySize, GEMM_SMEM);

    // 0) pre-split/pre-swizzle weights
    pack_w_k<<<1280, 256>>>(Wq, Wk, Wv, aW, fW, dW);

    // 1) QKV on shifted tokens -> g_Q/g_K/g_V (bias included)
    gemm_mma<MQKV, 512><<<dim3(TOKS / 128, 6, 1), 256, GEMM_SMEM>>>(
        x, bq, bk, bv, 0ull);

    // 2) windowed attention -> g_Z
    attn_k<<<8192, 256>>>();

    // 3) attn proj -> g_S ; LN + reverse shift + relu(x + .) -> g_z1
    gemm_mma<MPROJ, 256><<<dim3(TOKS / 128, 4, 1), 256, GEMM_SMEM>>>(
        nullptr, ab, nullptr, nullptr, 98304ull * 16);
    ln_k<0><<<TOKS, 128>>>(x, ag, abeta, nullptr);

    // 4) FFN -> g_S ; LN + relu(z1 + .) -> g_o2
    gemm_mma<MFFN, 512><<<dim3(TOKS / 128, 4, 1), 256, GEMM_SMEM>>>(
        nullptr, fb, nullptr, nullptr, 131072ull * 16);
    ln_k<1><<<TOKS, 128>>>(nullptr, fg, fbeta, nullptr);

    // 5) patch merge -> g_S ; LN + relu -> out
    gemm_mma<MMERGE, 1024><<<dim3(TOKS / 256, 4, 1), 256, GEMM_SMEM>>>(
        nullptr, db, nullptr, nullptr, 196608ull * 16);
    ln_k<2><<<TOKS / 2, 128>>>(nullptr, dg, dbeta, out);
}

// round 10
// speedup vs baseline: 5.3701x; 1.0007x over previous
#include <cuda_runtime.h>
#include <cuda_fp16.h>
#include <math.h>
#include <stdint.h>

// Problem constants
#define PP   256        // patches per (b,m)
#define DD   512        // model dim
#define HA   256        // H*A
#define TOKS 65536      // B*M*P

enum { MQKV = 0, MPROJ = 1, MFFN = 2, MMERGE = 3 };

// ---------------- scratch (device globals; allocation-free rule) -------------
__device__ float g_Q[(size_t)TOKS * HA];
__device__ float g_K[(size_t)TOKS * HA];
__device__ float g_V[(size_t)TOKS * HA];
__device__ float g_Z[(size_t)TOKS * HA];
__device__ float g_z1[(size_t)TOKS * DD];
__device__ float g_o2[(size_t)TOKS * DD];
__device__ float g_S[(size_t)TOKS * DD];      // raw GEMM output (pre-LN)
// packed split-fp16 weights: per mat [kchunk(32)][split(hi/lo)][n][4 x 16B units,
// unit ku stored at slot ku ^ ((n>>1)&3)]  -> 4*K*N bytes per mat, 5MB total
__device__ __align__(16) unsigned char g_Wpack[5u << 20];

// ---------------- helpers ----------------------------------------------------
__device__ __forceinline__ uint32_t smem_to_u32(const void* p) {
    uint32_t a;
    asm("{ .reg .u64 t; cvta.to.shared.u64 t, %1; cvt.u32.u64 %0, t; }" : "=r"(a) : "l"(p));
    return a;
}
__device__ __forceinline__ void cp16(uint32_t saddr, const void* g) {
    asm volatile("cp.async.cg.shared.global [%0], [%1], 16;" :: "r"(saddr), "l"(g));
}
__device__ __forceinline__ void cp_commit() { asm volatile("cp.async.commit_group;"); }
__device__ __forceinline__ void cp_wait0()  { asm volatile("cp.async.wait_group 0;" ::: "memory"); }

__device__ __forceinline__ void ldm4(uint32_t* d, uint32_t addr) {
    asm volatile("ldmatrix.sync.aligned.m8n8.x4.shared.b16 {%0,%1,%2,%3}, [%4];"
        : "=r"(d[0]), "=r"(d[1]), "=r"(d[2]), "=r"(d[3]) : "r"(addr));
}
__device__ __forceinline__ void mma16816(float* c, const uint32_t* a, uint32_t b0, uint32_t b1) {
    asm volatile("mma.sync.aligned.m16n8k16.row.col.f32.f16.f16.f32 "
        "{%0,%1,%2,%3}, {%4,%5,%6,%7}, {%8,%9}, {%0,%1,%2,%3};"
        : "+f"(c[0]), "+f"(c[1]), "+f"(c[2]), "+f"(c[3])
        : "r"(a[0]), "r"(a[1]), "r"(a[2]), "r"(a[3]), "r"(b0), "r"(b1));
}

// 8 fp32 -> 8 fp16 (one 16B unit)
__device__ __forceinline__ uint4 cvt8h(const float4 a, const float4 b) {
    const float f[8] = {a.x, a.y, a.z, a.w, b.x, b.y, b.z, b.w};
    uint32_t w[4];
    #pragma unroll
    for (int i = 0; i < 4; i++) {
        const __half h0 = __float2half_rn(f[2 * i]);
        const __half h1 = __float2half_rn(f[2 * i + 1]);
        w[i] = (uint32_t)__half_as_ushort(h0) | ((uint32_t)__half_as_ushort(h1) << 16);
    }
    return make_uint4(w[0], w[1], w[2], w[3]);
}
// 8 fp32 -> split hi/lo fp16 units
__device__ __forceinline__ void split8h(const float4 a, const float4 b, uint4& H, uint4& L) {
    const float f[8] = {a.x, a.y, a.z, a.w, b.x, b.y, b.z, b.w};
    uint32_t hw[4], lw[4];
    #pragma unroll
    for (int i = 0; i < 4; i++) {
        const float x0 = f[2 * i], x1 = f[2 * i + 1];
        const __half h0 = __float2half_rn(x0), h1 = __float2half_rn(x1);
        const __half l0 = __float2half_rn(x0 - __half2float(h0));
        const __half l1 = __float2half_rn(x1 - __half2float(h1));
        hw[i] = (uint32_t)__half_as_ushort(h0) | ((uint32_t)__half_as_ushort(h1) << 16);
        lw[i] = (uint32_t)__half_as_ushort(l0) | ((uint32_t)__half_as_ushort(l1) << 16);
    }
    H = make_uint4(hw[0], hw[1], hw[2], hw[3]);
    L = make_uint4(lw[0], lw[1], lw[2], lw[3]);
}

// =============================================================================
// Weight pre-pack: fp32 W[N][K] -> split fp16 chunks ready for cp.async.
// unit = 16B (8 fp16). dst unit = seg + ((c*2+split)*N + n)*4 + (ku ^ ((n>>1)&3))
// =============================================================================
__global__ void pack_w_k(const float* __restrict__ Wq, const float* __restrict__ Wk,
                         const float* __restrict__ Wv, const float* __restrict__ aW,
                         const float* __restrict__ fW, const float* __restrict__ dW) {
    const int u = blockIdx.x * 256 + threadIdx.x;   // logical unit, 327680 total
    const float* W; int N, K, seg;
    if      (u < 32768)  { W = Wq; N = 256; K = 512;  seg = 0; }
    else if (u < 65536)  { W = Wk; N = 256; K = 512;  seg = 32768; }
    else if (u < 98304)  { W = Wv; N = 256; K = 512;  seg = 65536; }
    else if (u < 131072) { W = aW; N = 512; K = 256;  seg = 98304; }
    else if (u < 196608) { W = fW; N = 512; K = 512;  seg = 131072; }
    else                 { W = dW; N = 512; K = 1024; seg = 196608; }
    const int lu = u - seg;
    const int c     = lu / (8 * N);
    const int rem   = lu % (8 * N);
    const int split = rem / (4 * N);
    const int rem2  = rem % (4 * N);
    const int n  = rem2 >> 2, ku = rem2 & 3;
    const float* src = W + (size_t)n * K + c * 32 + ku * 8;
    const float4 a = *(const float4*)src;
    const float4 b = *(const float4*)(src + 4);
    uint4 H, L;
    split8h(a, b, H, L);
    const size_t dst = ((size_t)seg + ((size_t)(c * 2 + split) * N + n) * 4 + (ku ^ ((n >> 1) & 3))) * 16;
    *(uint4*)(g_Wpack + dst) = (split == 0) ? H : L;
}

// =============================================================================
// Tensor-core GEMM via mma.sync, 2-term fp16 (A single, B = hi+lo split).
// CTA tile 128x128, KC=32, double-buffered. 8 warps: 2(m) x 4(n), warp 64x32.
// =============================================================================
template<int MODE, int K>
__global__ void __launch_bounds__(256, 2) gemm_mma(
    const float* __restrict__ Ax,
    const float* __restrict__ b0, const float* __restrict__ b1,
    const float* __restrict__ b2, size_t wofs)
{
    constexpr int CH = K / 32;
    constexpr int NMAT = (MODE == MQKV) ? 256 : 512;
    constexpr uint32_t SA = 0;          // [2][128 rows x 64B]        16KB
    constexpr uint32_t SB = 16384;      // [2][2 planes][128 x 64B]   32KB
    constexpr uint32_t SBIAS = 49152;

    extern __shared__ __align__(16) unsigned char smem[];
    const uint32_t sb = smem_to_u32(smem);
    const int tid = threadIdx.x, lane = tid & 31, w = tid >> 5;
    const int wm = w >> 2, wn = w & 3;
    const int bx = blockIdx.x, nb = blockIdx.y;

    size_t wseg = wofs;
    int nloc0;
    const float* Bias;
    float* Obuf;
    if constexpr (MODE == MQKV) {
        const int mat = nb >> 1;
        wseg += (size_t)mat * (512u << 10);
        nloc0 = (nb & 1) * 128;
        Bias = (mat == 0) ? b0 : (mat == 1) ? b1 : b2;
        Obuf = (mat == 0) ? g_Q : (mat == 1) ? g_K : g_V;
    } else {
        nloc0 = nb * 128;
        Bias = b0;
        Obuf = g_S;
    }
    if (tid < 128) ((float*)(smem + SBIAS))[tid] = Bias[nloc0 + tid];

    // ---- A staging identity: thread -> (row r, half hh) : 16 fp32 per chunk
    const int r = tid >> 1, hh = tid & 1;
    const int rgl = bx * 128 + r;
    const float* arow = nullptr;
    int mtok = 0;
    if constexpr (MODE == MQKV) {
        const int srow = (rgl & ~(PP - 1)) | ((rgl + 2) & (PP - 1));   // roll(x,-2)
        arow = Ax + (size_t)srow * DD;
    } else if constexpr (MODE == MPROJ) {
        arow = g_Z + (size_t)rgl * HA;
    } else if constexpr (MODE == MFFN) {
        arow = g_z1 + (size_t)rgl * DD;
    } else {
        mtok = ((rgl >> 7) << 8) + ((rgl & 127) << 1);
    }

    // ---- ldmatrix per-thread address components
    const int am = lane >> 3, atr = lane & 7;
    int aRow[4], aSw[4], bRow[2], bSw[2];
    #pragma unroll
    for (int i = 0; i < 4; i++) {
        const int row = wm * 64 + i * 16 + (am & 1) * 8 + atr;
        aRow[i] = row * 64; aSw[i] = (row >> 1) & 3;
    }
    #pragma unroll
    for (int p = 0; p < 2; p++) {
        const int n = wn * 32 + p * 16 + (am >> 1) * 8 + atr;
        bRow[p] = n * 64; bSw[p] = (n >> 1) & 3;
    }
    const int akb = am >> 1;   // A k-unit bit
    const int bkb = am & 1;    // B k-unit bit

    float acc[4][4][4];
    #pragma unroll
    for (int i = 0; i < 4; i++)
        #pragma unroll
        for (int j = 0; j < 4; j++)
            #pragma unroll
            for (int e = 0; e < 4; e++) acc[i][j][e] = 0.f;

    float4 av[4];
    auto ldgA = [&](int c) {
        const float* ap;
        if constexpr (MODE == MMERGE)
            ap = g_o2 + (size_t)(mtok + (c >> 4)) * DD + ((c & 15) * 32 + hh * 16);
        else
            ap = arow + c * 32 + hh * 16;
        #pragma unroll
        for (int i = 0; i < 4; i++) av[i] = __ldg((const float4*)(ap + i * 4));
    };
    auto stsA = [&](int buf) {
        #pragma unroll
        for (int g = 0; g < 2; g++) {
            const uint4 H = cvt8h(av[2 * g], av[2 * g + 1]);
            const int ku = hh * 2 + g;
            const int su = ku ^ ((r >> 1) & 3);
            *(uint4*)(smem + SA + buf * 8192 + r * 64 + su * 16) = H;
        }
    };
    auto cpB = [&](int c, int buf) {
        #pragma unroll
        for (int k = 0; k < 4; k++) {
            const int i = tid + k * 256;           // 0..1023 units (2 planes x 512)
            const int s = i >> 9, rs = i & 511;
            cp16(sb + SB + buf * 16384 + s * 8192 + rs * 16,
                 g_Wpack + wseg + (((size_t)(c * 2 + s) * NMAT + nloc0) << 6) + ((size_t)rs << 4));
        }
        cp_commit();
    };
    auto compute = [&](int buf) {
        const uint32_t ab0 = sb + SA + buf * 8192;
        const uint32_t bh0 = sb + SB + buf * 16384;
        const uint32_t bl0 = bh0 + 8192;
        #pragma unroll
        for (int ks = 0; ks < 2; ks++) {
            uint32_t ah[4][4], bh[2][4], bl[2][4];
            const int kua = ks * 2 + akb, kub = ks * 2 + bkb;
            #pragma unroll
            for (int i = 0; i < 4; i++) ldm4(ah[i], ab0 + aRow[i] + ((kua ^ aSw[i]) << 4));
            #pragma unroll
            for (int p = 0; p < 2; p++) {
                ldm4(bh[p], bh0 + bRow[p] + ((kub ^ bSw[p]) << 4));
                ldm4(bl[p], bl0 + bRow[p] + ((kub ^ bSw[p]) << 4));
            }
            #pragma unroll
            for (int i = 0; i < 4; i++)
                #pragma unroll
                for (int j = 0; j < 4; j++)
                    mma16816(acc[i][j], ah[i], bh[j >> 1][(j & 1) * 2], bh[j >> 1][(j & 1) * 2 + 1]);
            #pragma unroll
            for (int i = 0; i < 4; i++)
                #pragma unroll
                for (int j = 0; j < 4; j++)
                    mma16816(acc[i][j], ah[i], bl[j >> 1][(j & 1) * 2], bl[j >> 1][(j & 1) * 2 + 1]);
        }
    };

    // ---- pipeline
    ldgA(0);
    cpB(0, 0);
    stsA(0);
    cp_wait0();
    __syncthreads();
    int buf = 0;
    for (int c = 0; c < CH; c++) {
        if (c + 1 < CH) { ldgA(c + 1); cpB(c + 1, buf ^ 1); }
        compute(buf);
        if (c + 1 < CH) { stsA(buf ^ 1); cp_wait0(); }
        __syncthreads();
        buf ^= 1;
    }

    // ---- epilogue: bias + store fp32
    const float* sBias = (const float*)(smem + SBIAS);
    #pragma unroll
    for (int i = 0; i < 4; i++) {
        const int row0 = bx * 128 + wm * 64 + i * 16 + (lane >> 2);
        #pragma unroll
        for (int j = 0; j < 4; j++) {
            const int cl = wn * 32 + j * 8 + 2 * (lane & 3);
            const float bb0 = sBias[cl], bb1 = sBias[cl + 1];
            float* p0;
            int stride;
            if constexpr (MODE == MQKV) {
                p0 = Obuf + (size_t)row0 * 256 + (nb & 1) * 128 + cl;
                stride = 8 * 256;
            } else {
                p0 = Obuf + (size_t)row0 * 512 + nloc0 + cl;
                stride = 8 * 512;
            }
            *(float2*)p0            = make_float2(acc[i][j][0] + bb0, acc[i][j][1] + bb1);
            *(float2*)(p0 + stride) = make_float2(acc[i][j][2] + bb0, acc[i][j][3] + bb1);
        }
    }
}

// =============================================================================
// Fused LayerNorm passes (128 threads per row of 512)
// MODE 0: g_z1[dtok] = relu(x[dtok] + LN(g_S[row]))   (reverse shift +2)
// MODE 1: g_o2[row]  = relu(g_z1[row] + LN(g_S[row]))
// MODE 2: Out[row]   = relu(LN(g_S[row]))
// =============================================================================
template<int MODE>
__global__ void __launch_bounds__(128) ln_k(const float* __restrict__ X,
                                            const float* __restrict__ gamma,
                                            const float* __restrict__ beta,
                                            float* __restrict__ Out)
{
    const int row = blockIdx.x, tid = threadIdx.x;
    const int lane = tid & 31, wid = tid >> 5;
    const float4 v = *(const float4*)(g_S + (size_t)row * DD + tid * 4);
    float s = v.x + v.y + v.z + v.w;
    float q = v.x * v.x + v.y * v.y + v.z * v.z + v.w * v.w;
    #pragma unroll
    for (int m = 16; m >= 1; m >>= 1) {
        s += __shfl_xor_sync(0xffffffffu, s, m);
        q += __shfl_xor_sync(0xffffffffu, q, m);
    }
    __shared__ float2 red[4];
    if (lane == 0) red[wid] = make_float2(s, q);
    __syncthreads();
    float S = 0.f, Q = 0.f;
    #pragma unroll
    for (int k = 0; k < 4; k++) { S += red[k].x; Q += red[k].y; }
    const float mu = S * (1.0f / DD);
    const float var = Q * (1.0f / DD) - mu * mu;
    const float rs = rsqrtf(var + 1e-5f);
    const float4 g = *(const float4*)(gamma + tid * 4);
    const float4 b = *(const float4*)(beta + tid * 4);
    float4 o = make_float4((v.x - mu) * rs * g.x + b.x, (v.y - mu) * rs * g.y + b.y,
                           (v.z - mu) * rs * g.z + b.z, (v.w - mu) * rs * g.w + b.w);
    if constexpr (MODE == 0) {
        const int dtok = (row & ~(PP - 1)) | ((row + 2) & (PP - 1));
        const float4 xr = *(const float4*)(X + (size_t)dtok * DD + tid * 4);
        *(float4*)(g_z1 + (size_t)dtok * DD + tid * 4) = make_float4(
            fmaxf(xr.x + o.x, 0.f), fmaxf(xr.y + o.y, 0.f),
            fmaxf(xr.z + o.z, 0.f), fmaxf(xr.w + o.w, 0.f));
    } else if constexpr (MODE == 1) {
        const float4 zr = *(const float4*)(g_z1 + (size_t)row * DD + tid * 4);
        *(float4*)(g_o2 + (size_t)row * DD + tid * 4) = make_float4(
            fmaxf(zr.x + o.x, 0.f), fmaxf(zr.y + o.y, 0.f),
            fmaxf(zr.z + o.z, 0.f), fmaxf(zr.w + o.w, 0.f));
    } else {
        *(float4*)(Out + (size_t)row * DD + tid * 4) = make_float4(
            fmaxf(o.x, 0.f), fmaxf(o.y, 0.f), fmaxf(o.z, 0.f), fmaxf(o.w, 0.f));
    }
}

// =============================================================================
// Windowed attention: 1 warp per (window, head). WS=4, A=64.
// =============================================================================
__global__ void __launch_bounds__(256) attn_k() {
    const int task = blockIdx.x * 8 + (threadIdx.x >> 5);
    const int lane = threadIdx.x & 31;
    const int w = task >> 2, h = task & 3;
    const size_t base = (size_t)(w << 2) * HA + (h << 6) + lane;

    float q0[4], q1[4], k0v[4], k1v[4], v0[4], v1[4];
    #pragma unroll
    for (int r = 0; r < 4; r++) {
        q0[r]  = g_Q[base + (size_t)r * HA];  q1[r]  = g_Q[base + (size_t)r * HA + 32];
        k0v[r] = g_K[base + (size_t)r * HA];  k1v[r] = g_K[base + (size_t)r * HA + 32];
        v0[r]  = g_V[base + (size_t)r * HA];  v1[r]  = g_V[base + (size_t)r * HA + 32];
    }
    float s[4][4];
    #pragma unroll
    for (int r = 0; r < 4; r++)
        #pragma unroll
        for (int c = 0; c < 4; c++) {
            float p = q0[r] * k0v[c] + q1[r] * k1v[c];
            #pragma unroll
            for (int m = 16; m >= 1; m >>= 1) p += __shfl_xor_sync(0xffffffffu, p, m);
            s[r][c] = p * 0.125f;
        }
    if ((w & 63) == 63) {
        #pragma unroll
        for (int r = 0; r < 4; r++)
            #pragma unroll
            for (int c = 0; c < 4; c++)
                if ((r < 2) != (c < 2)) s[r][c] -= 100.0f;
    }
    #pragma unroll
    for (int r = 0; r < 4; r++) {
        const float m = fmaxf(fmaxf(s[r][0], s[r][1]), fmaxf(s[r][2], s[r][3]));
        const float e0 = expf(s[r][0] - m), e1 = expf(s[r][1] - m);
        const float e2 = expf(s[r][2] - m), e3 = expf(s[r][3] - m);
        const float inv = 1.0f / (e0 + e1 + e2 + e3);
        g_Z[base + (size_t)r * HA]      = (e0 * v0[0] + e1 * v0[1] + e2 * v0[2] + e3 * v0[3]) * inv;
        g_Z[base + (size_t)r * HA + 32] = (e0 * v1[0] + e1 * v1[1] + e2 * v1[2] + e3 * v1[3]) * inv;
    }
}

// =============================================================================
#define GEMM_SMEM (49152 + 512)

extern "C" void kernel_launch(void* const* d_in, const int* in_sizes, int n_in,
                              void* d_out, int out_size) {
    (void)in_sizes; (void)n_in; (void)out_size;
    const float* x     = (const float*)d_in[0];
    const float* Wq    = (const float*)d_in[1];
    const float* bq    = (const float*)d_in[2];
    const float* Wk    = (const float*)d_in[3];
    const float* bk    = (const float*)d_in[4];
    const float* Wv    = (const float*)d_in[5];
    const float* bv    = (const float*)d_in[6];
    const float* aW    = (const float*)d_in[7];
    const float* ab    = (const float*)d_in[8];
    const float* ag    = (const float*)d_in[9];
    const float* abeta = (const float*)d_in[10];
    const float* fW    = (const float*)d_in[11];
    const float* fb    = (const float*)d_in[12];
    const float* fg    = (const float*)d_in[13];
    const float* fbeta = (const float*)d_in[14];
    const float* dW    = (const float*)d_in[15];
    const float* db    = (const float*)d_in[16];
    const float* dg    = (const float*)d_in[17];
    const float* dbeta = (const float*)d_in[18];
    float* out = (float*)d_out;

    cudaFuncSetAttribute(gemm_mma<MQKV, 512>,   cudaFuncAttributeMaxDynamicSharedMemorySize, GEMM_SMEM);
    cudaFuncSetAttribute(gemm_mma<MPROJ, 256>,  cudaFuncAttributeMaxDynamicSharedMemorySize, GEMM_SMEM);
    cudaFuncSetAttribute(gemm_mma<MFFN, 512>,   cudaFuncAttributeMaxDynamicSharedMemorySize, GEMM_SMEM);
    cudaFuncSetAttribute(gemm_mma<MMERGE, 1024>, cudaFuncAttributeMaxDynamicSharedMemorySize, GEMM_SMEM);

    // 0) pre-split/pre-swizzle weights
    pack_w_k<<<1280, 256>>>(Wq, Wk, Wv, aW, fW, dW);

    // 1) QKV on shifted tokens -> g_Q/g_K/g_V (bias included)
    gemm_mma<MQKV, 512><<<dim3(TOKS / 128, 6, 1), 256, GEMM_SMEM>>>(
        x, bq, bk, bv, 0ull);

    // 2) windowed attention -> g_Z
    attn_k<<<8192, 256>>>();

    // 3) attn proj -> g_S ; LN + reverse shift + relu(x + .) -> g_z1
    gemm_mma<MPROJ, 256><<<dim3(TOKS / 128, 4, 1), 256, GEMM_SMEM>>>(
        nullptr, ab, nullptr, nullptr, 98304ull * 16);
    ln_k<0><<<TOKS, 128>>>(x, ag, abeta, nullptr);

    // 4) FFN -> g_S ; LN + relu(z1 + .) -> g_o2
    gemm_mma<MFFN, 512><<<dim3(TOKS / 128, 4, 1), 256, GEMM_SMEM>>>(
        nullptr, fb, nullptr, nullptr, 131072ull * 16);
    ln_k<1><<<TOKS, 128>>>(nullptr, fg, fbeta, nullptr);

    // 5) patch merge -> g_S ; LN + relu -> out
    gemm_mma<MMERGE, 1024><<<dim3(TOKS / 256, 4, 1), 256, GEMM_SMEM>>>(
        nullptr, db, nullptr, nullptr, 196608ull * 16);
    ln_k<2><<<TOKS / 2, 128>>>(nullptr, dg, dbeta, out);
}